// round 1
// baseline (speedup 1.0000x reference)
#include <cuda_runtime.h>
#include <cuda_bf16.h>
#include <cstdint>

#define NN 50000
#define EE 800000
#define RR 4
#define GG 16

// ---------------- scratch (device globals; no allocation) ----------------
__device__ float          g_YA[NN * 640];          // 128 MB
__device__ float          g_YB[NN * 640];          // 128 MB
__device__ __nv_bfloat16  g_Asp[NN * 256];         // split activations [N][Ah(128)|Al(128)]
__device__ __nv_bfloat16  g_Bsp[256 * 640];        // split weights     [Bh(128)|Bl(128)][5*out]
__device__ float          g_q[GG * 64];
__device__ int            g_cnt[RR * NN];
__device__ float          g_inv[NN * 4];           // [node][relation] 1/max(cnt,1)
__device__ int            g_rowptr[NN + 1];
__device__ int            g_fill[NN];
__device__ int            g_csr[EE];               // src | (rel<<28)

// ---------------- small helpers ----------------
__device__ __forceinline__ uint32_t smem_u32(const void* p) {
    return (uint32_t)__cvta_generic_to_shared(p);
}
__device__ __forceinline__ void ldsm4(uint32_t* d, const __nv_bfloat16* p) {
    uint32_t a = smem_u32(p);
    asm volatile("ldmatrix.sync.aligned.m8n8.x4.shared.b16 {%0,%1,%2,%3}, [%4];"
                 : "=r"(d[0]), "=r"(d[1]), "=r"(d[2]), "=r"(d[3]) : "r"(a));
}
__device__ __forceinline__ void ldsm4t(uint32_t* d, const __nv_bfloat16* p) {
    uint32_t a = smem_u32(p);
    asm volatile("ldmatrix.sync.aligned.m8n8.x4.trans.shared.b16 {%0,%1,%2,%3}, [%4];"
                 : "=r"(d[0]), "=r"(d[1]), "=r"(d[2]), "=r"(d[3]) : "r"(a));
}
__device__ __forceinline__ void mma16816(float* c, const uint32_t* a, uint32_t b0, uint32_t b1) {
    asm volatile(
        "mma.sync.aligned.m16n8k16.row.col.f32.bf16.bf16.f32 "
        "{%0,%1,%2,%3}, {%4,%5,%6,%7}, {%8,%9}, {%0,%1,%2,%3};"
        : "+f"(c[0]), "+f"(c[1]), "+f"(c[2]), "+f"(c[3])
        : "r"(a[0]), "r"(a[1]), "r"(a[2]), "r"(a[3]), "r"(b0), "r"(b1));
}
__device__ __forceinline__ float pick4(float4 v, int r) {
    return r == 0 ? v.x : (r == 1 ? v.y : (r == 2 ? v.z : v.w));
}

// ---------------- CSR build ----------------
__global__ void k_zero_cnt() {
    int i = blockIdx.x * blockDim.x + threadIdx.x;
    if (i < RR * NN) g_cnt[i] = 0;
}
__global__ void k_count(const int* __restrict__ dst, const int* __restrict__ ea) {
    int e = blockIdx.x * blockDim.x + threadIdx.x;
    if (e >= EE) return;
    atomicAdd(&g_cnt[ea[e] * NN + dst[e]], 1);
}
__global__ void k_scan() {
    __shared__ int s[1024];
    const int CH = (NN + 1023) / 1024;   // 49
    int t = threadIdx.x;
    int lo = t * CH, hi = min(lo + CH, NN);
    int sum = 0;
    for (int i = lo; i < hi; i++) {
        int tot = 0;
#pragma unroll
        for (int r = 0; r < RR; r++) {
            int c = g_cnt[r * NN + i];
            tot += c;
            g_inv[i * 4 + r] = 1.0f / (float)max(c, 1);
        }
        sum += tot;
    }
    s[t] = sum;
    __syncthreads();
    for (int d = 1; d < 1024; d <<= 1) {
        int v = (t >= d) ? s[t - d] : 0;
        __syncthreads();
        s[t] += v;
        __syncthreads();
    }
    int off = (t == 0) ? 0 : s[t - 1];
    for (int i = lo; i < hi; i++) {
        g_rowptr[i] = off;
        g_fill[i] = off;
        int tot = 0;
#pragma unroll
        for (int r = 0; r < RR; r++) tot += g_cnt[r * NN + i];
        off += tot;
    }
    if (t == 1023) g_rowptr[NN] = s[1023];
}
__global__ void k_fill(const int* __restrict__ src, const int* __restrict__ dst,
                       const int* __restrict__ ea) {
    int e = blockIdx.x * blockDim.x + threadIdx.x;
    if (e >= EE) return;
    int d = dst[e];
    int pos = atomicAdd(&g_fill[d], 1);
    g_csr[pos] = src[e] | (ea[e] << 28);
}

// ---------------- question projection: q = relu(qe @ qn_W + qn_b) ----------------
__global__ void k_q(const float* __restrict__ qe, const float* __restrict__ qnW,
                    const float* __restrict__ qnb) {
    __shared__ float sq[768];
    int g = blockIdx.x, j = threadIdx.x;
    for (int i = j; i < 768; i += 64) sq[i] = qe[g * 768 + i];
    __syncthreads();
    float acc = qnb[j];
    for (int k = 0; k < 768; k++) acc = fmaf(sq[k], qnW[k * 64 + j], acc);
    g_q[g * 64 + j] = fmaxf(acc, 0.0f);
}

// ---------------- activation split (with per-layer input semantics) ----------------
template <int MODE>
__global__ void k_prepA(const float* __restrict__ x, const int* __restrict__ batch) {
    int idx = blockIdx.x * blockDim.x + threadIdx.x;
    if (idx >= NN * 128) return;
    int i = idx >> 7, k = idx & 127;
    float v;
    if (MODE == 0) v = x[idx];
    else if (MODE == 1) v = (k < 64) ? fmaxf(g_YA[i * 320 + k], 0.0f)
                                     : g_q[batch[i] * 64 + (k - 64)];
    else if (MODE == 2) v = fmaxf(g_YB[i * 640 + k], 0.0f);
    else                v = fmaxf(g_YA[i * 640 + k], 0.0f);
    __nv_bfloat16 hi = __float2bfloat16(v);
    float lo = v - __bfloat162float(hi);
    g_Asp[i * 256 + k]       = hi;
    g_Asp[i * 256 + 128 + k] = __float2bfloat16(lo);
}

// ---------------- weight concat + split: [root | W0..W3] ----------------
__global__ void k_prepB(const float* __restrict__ root, const float* __restrict__ W, int out) {
    int ncols = 5 * out;
    int idx = blockIdx.x * blockDim.x + threadIdx.x;
    if (idx >= 256 * ncols) return;
    int k2 = idx / ncols, j = idx % ncols;
    int k = k2 & 127;
    float v = (j < out) ? root[k * out + j]
                        : W[((j / out - 1) * 128 + k) * out + (j % out)];
    __nv_bfloat16 h = __float2bfloat16(v);
    if (k2 >= 128) h = __float2bfloat16(v - __bfloat162float(h));
    g_Bsp[k2 * ncols + j] = h;
}

// ---------------- GEMM: Y[N, ncols] = Asp @ Bsp (3-term bf16 split, K'=384) ----------------
#define AST 264   // 256 + 8 pad (bf16 elems)
#define BST 72    // 64 + 8 pad
#define GEMM_SMEM ((128 * AST + 256 * BST) * 2)

__global__ void __launch_bounds__(256) k_gemm(float* __restrict__ Y,
                                              const float* __restrict__ bias,
                                              int ncols, int out) {
    extern __shared__ __nv_bfloat16 smem[];
    __nv_bfloat16* sA = smem;                 // [128][AST]
    __nv_bfloat16* sB = smem + 128 * AST;     // [256][BST]
    int m0 = blockIdx.x * 128;
    int n0 = blockIdx.y * 64;
    int t = threadIdx.x;

    // load A tile (128 x 256 bf16), zero-padded rows beyond N
#pragma unroll
    for (int v = 0; v < 16; v++) {
        int fidx = v * 256 + t;
        int row = fidx >> 5;
        int c8 = (fidx & 31) * 8;
        int grow = m0 + row;
        uint4 val = make_uint4(0, 0, 0, 0);
        if (grow < NN) val = *(const uint4*)(g_Asp + (size_t)grow * 256 + c8);
        *(uint4*)(sA + row * AST + c8) = val;
    }
    // load B tile (256 x 64 bf16)
#pragma unroll
    for (int v = 0; v < 8; v++) {
        int fidx = v * 256 + t;
        int row = fidx >> 3;
        int c8 = (fidx & 7) * 8;
        uint4 val = *(const uint4*)(g_Bsp + (size_t)row * ncols + n0 + c8);
        *(uint4*)(sB + row * BST + c8) = val;
    }
    __syncthreads();

    int w = t >> 5, lane = t & 31;
    int wm = (w & 3) * 32, wn = (w >> 2) * 32;
    int lr = lane & 15, lc = lane >> 4;

    float acc[2][4][4];
#pragma unroll
    for (int mt = 0; mt < 2; mt++)
#pragma unroll
        for (int nt = 0; nt < 4; nt++)
#pragma unroll
            for (int i = 0; i < 4; i++) acc[mt][nt][i] = 0.0f;

#pragma unroll
    for (int s = 0; s < 3; s++) {
        int aBase = (s == 1) ? 128 : 0;   // seg0: Ah*Bh, seg1: Al*Bh, seg2: Ah*Bl
        int bBase = (s == 2) ? 128 : 0;
#pragma unroll
        for (int kk = 0; kk < 8; kk++) {
            int ka = aBase + kk * 16;
            int kb = bBase + kk * 16;
            uint32_t a[2][4], b[2][4];
#pragma unroll
            for (int mt = 0; mt < 2; mt++)
                ldsm4(a[mt], sA + (wm + mt * 16 + lr) * AST + ka + lc * 8);
#pragma unroll
            for (int nh = 0; nh < 2; nh++)
                ldsm4t(b[nh], sB + (kb + lr) * BST + wn + nh * 16 + lc * 8);
#pragma unroll
            for (int mt = 0; mt < 2; mt++)
#pragma unroll
                for (int nt = 0; nt < 4; nt++) {
                    int nh = nt >> 1, h = (nt & 1) * 2;
                    mma16816(acc[mt][nt], a[mt], b[nh][h], b[nh][h + 1]);
                }
        }
    }

    // epilogue: write fp32 (+bias on self block cols < out)
    int g = lane >> 2, tg = lane & 3;
#pragma unroll
    for (int mt = 0; mt < 2; mt++) {
#pragma unroll
        for (int nt = 0; nt < 4; nt++) {
            int col = n0 + wn + nt * 8 + tg * 2;
            float b0 = (col < out) ? bias[col] : 0.0f;
            float b1 = (col < out) ? bias[col + 1] : 0.0f;
            int r0 = m0 + wm + mt * 16 + g;
            if (r0 < NN) {
                Y[(size_t)r0 * ncols + col]     = acc[mt][nt][0] + b0;
                Y[(size_t)r0 * ncols + col + 1] = acc[mt][nt][1] + b1;
            }
            int r1 = r0 + 8;
            if (r1 < NN) {
                Y[(size_t)r1 * ncols + col]     = acc[mt][nt][2] + b0;
                Y[(size_t)r1 * ncols + col + 1] = acc[mt][nt][3] + b1;
            }
        }
    }
}

// ---------------- pull aggregation: one warp per node ----------------
template <int OUT>
__global__ void __launch_bounds__(256) k_agg(const float* __restrict__ Y, int ld,
                                             float* __restrict__ O, int lo_) {
    int w = (blockIdx.x * 256 + threadIdx.x) >> 5;
    if (w >= NN) return;
    int lane = threadIdx.x & 31;
    constexpr int V = OUT / 32;   // 4 or 2 floats per lane
    int start = g_rowptr[w], end = g_rowptr[w + 1];
    float4 iv4 = *(const float4*)(g_inv + w * 4);

    float acc[V];
    const float* selfp = Y + (size_t)w * ld + lane * V;
    if (V == 4) {
        float4 s = *(const float4*)selfp;
        acc[0] = s.x; acc[1] = s.y; acc[2] = s.z; acc[3] = s.w;
    } else {
        float2 s = *(const float2*)selfp;
        acc[0] = s.x; acc[1] = s.y;
    }

    int e = start;
    for (; e + 2 <= end; e += 2) {
        int u0 = g_csr[e], u1 = g_csr[e + 1];
        int s0 = u0 & 0x0FFFFFFF, r0 = ((unsigned)u0) >> 28;
        int s1 = u1 & 0x0FFFFFFF, r1 = ((unsigned)u1) >> 28;
        const float* p0 = Y + (size_t)s0 * ld + (1 + r0) * OUT + lane * V;
        const float* p1 = Y + (size_t)s1 * ld + (1 + r1) * OUT + lane * V;
        float i0 = pick4(iv4, r0), i1 = pick4(iv4, r1);
        if (V == 4) {
            float4 m0 = *(const float4*)p0;
            float4 m1 = *(const float4*)p1;
            acc[0] += m0.x * i0; acc[1] += m0.y * i0;
            acc[2] += m0.z * i0; acc[3] += m0.w * i0;
            acc[0] += m1.x * i1; acc[1] += m1.y * i1;
            acc[2] += m1.z * i1; acc[3] += m1.w * i1;
        } else {
            float2 m0 = *(const float2*)p0;
            float2 m1 = *(const float2*)p1;
            acc[0] += m0.x * i0; acc[1] += m0.y * i0;
            acc[0] += m1.x * i1; acc[1] += m1.y * i1;
        }
    }
    if (e < end) {
        int u0 = g_csr[e];
        int s0 = u0 & 0x0FFFFFFF, r0 = ((unsigned)u0) >> 28;
        const float* p0 = Y + (size_t)s0 * ld + (1 + r0) * OUT + lane * V;
        float i0 = pick4(iv4, r0);
        if (V == 4) {
            float4 m0 = *(const float4*)p0;
            acc[0] += m0.x * i0; acc[1] += m0.y * i0;
            acc[2] += m0.z * i0; acc[3] += m0.w * i0;
        } else {
            float2 m0 = *(const float2*)p0;
            acc[0] += m0.x * i0; acc[1] += m0.y * i0;
        }
    }

    float* op = O + (size_t)w * lo_ + lane * V;
    if (V == 4) {
        float4 r; r.x = acc[0]; r.y = acc[1]; r.z = acc[2]; r.w = acc[3];
        *(float4*)op = r;
    } else {
        float2 r; r.x = acc[0]; r.y = acc[1];
        *(float2*)op = r;
    }
}

// ---------------- host orchestration ----------------
extern "C" void kernel_launch(void* const* d_in, const int* in_sizes, int n_in,
                              void* d_out, int out_size) {
    const float* x     = (const float*)d_in[0];
    const int*   ei    = (const int*)d_in[1];
    const int*   ea    = (const int*)d_in[2];
    const int*   batch = (const int*)d_in[3];
    const float* qe    = (const float*)d_in[4];
    const float* qnW   = (const float*)d_in[5];
    const float* qnb   = (const float*)d_in[6];
    const float* W0 = (const float*)d_in[7],  *root0 = (const float*)d_in[8],  *b0 = (const float*)d_in[9];
    const float* W1 = (const float*)d_in[10], *root1 = (const float*)d_in[11], *b1 = (const float*)d_in[12];
    const float* W2 = (const float*)d_in[13], *root2 = (const float*)d_in[14], *b2 = (const float*)d_in[15];
    const float* W3 = (const float*)d_in[16], *root3 = (const float*)d_in[17], *b3 = (const float*)d_in[18];
    float* out = (float*)d_out;

    const int* src = ei;
    const int* dst = ei + EE;

    float* YA; cudaGetSymbolAddress((void**)&YA, g_YA);
    float* YB; cudaGetSymbolAddress((void**)&YB, g_YB);

    cudaFuncSetAttribute(k_gemm, cudaFuncAttributeMaxDynamicSharedMemorySize, GEMM_SMEM);

    // CSR build + question projection
    k_zero_cnt<<<(RR * NN + 255) / 256, 256>>>();
    k_count<<<(EE + 255) / 256, 256>>>(dst, ea);
    k_scan<<<1, 1024>>>();
    k_fill<<<(EE + 255) / 256, 256>>>(src, dst, ea);
    k_q<<<GG, 64>>>(qe, qnW, qnb);

    const int MG = 391;                       // ceil(50000/128)
    const int AGG_G = (NN * 32 + 255) / 256;  // 6250

    // Layer 0: in=128, out=64 -> YA (ld 320)
    k_prepB<<<(256 * 320 + 255) / 256, 256>>>(root0, W0, 64);
    k_prepA<0><<<(NN * 128 + 255) / 256, 256>>>(x, batch);
    k_gemm<<<dim3(MG, 5), 256, GEMM_SMEM>>>(YA, b0, 320, 64);
    k_agg<64><<<AGG_G, 256>>>(YA, 320, YA, 320);

    // Layer 1: in=128 (relu(h)|q[batch]), out=128 -> YB (ld 640)
    k_prepB<<<(256 * 640 + 255) / 256, 256>>>(root1, W1, 128);
    k_prepA<1><<<(NN * 128 + 255) / 256, 256>>>(x, batch);
    k_gemm<<<dim3(MG, 10), 256, GEMM_SMEM>>>(YB, b1, 640, 128);
    k_agg<128><<<AGG_G, 256>>>(YB, 640, YB, 640);

    // Layer 2: in=128, out=128 -> YA (ld 640)
    k_prepB<<<(256 * 640 + 255) / 256, 256>>>(root2, W2, 128);
    k_prepA<2><<<(NN * 128 + 255) / 256, 256>>>(x, batch);
    k_gemm<<<dim3(MG, 10), 256, GEMM_SMEM>>>(YA, b2, 640, 128);
    k_agg<128><<<AGG_G, 256>>>(YA, 640, YA, 640);

    // Layer 3: in=128, out=64 -> YB (ld 320), aggregate into d_out
    k_prepB<<<(256 * 320 + 255) / 256, 256>>>(root3, W3, 64);
    k_prepA<3><<<(NN * 128 + 255) / 256, 256>>>(x, batch);
    k_gemm<<<dim3(MG, 5), 256, GEMM_SMEM>>>(YB, b3, 320, 64);
    k_agg<64><<<AGG_G, 256>>>(YB, 320, out, 64);
}

// round 2
// speedup vs baseline: 1.1712x; 1.1712x over previous
#include <cuda_runtime.h>
#include <cuda_bf16.h>
#include <cuda_fp16.h>
#include <cstdint>

#define NN 50000
#define EE 800000
#define RR 4
#define GG 16

// ---------------- scratch (device globals; no allocation) ----------------
__device__ float          g_Ys[NN * 128];          // self+bias, fp32 [N][out]
__device__ __half         g_Ym[NN * 512];          // messages, fp16 [N][4*out] (L2-resident: <=51MB)
__device__ __nv_bfloat16  g_Asp[NN * 256];         // split activations [N][Ah(128)|Al(128)]
__device__ __nv_bfloat16  g_Bsp[256 * 640];        // split weights     [Bh(128)|Bl(128)][5*out]
__device__ float          g_q[GG * 64];
__device__ int            g_cnt[RR * NN];
__device__ float          g_inv[NN * 4];           // [node][relation] 1/max(cnt,1)
__device__ int            g_rowptr[NN + 1];
__device__ int            g_fill[NN];
__device__ int            g_csr[EE];               // src | (rel<<28)

// ---------------- small helpers ----------------
__device__ __forceinline__ uint32_t smem_u32(const void* p) {
    return (uint32_t)__cvta_generic_to_shared(p);
}
__device__ __forceinline__ void ldsm4(uint32_t* d, const __nv_bfloat16* p) {
    uint32_t a = smem_u32(p);
    asm volatile("ldmatrix.sync.aligned.m8n8.x4.shared.b16 {%0,%1,%2,%3}, [%4];"
                 : "=r"(d[0]), "=r"(d[1]), "=r"(d[2]), "=r"(d[3]) : "r"(a));
}
__device__ __forceinline__ void ldsm4t(uint32_t* d, const __nv_bfloat16* p) {
    uint32_t a = smem_u32(p);
    asm volatile("ldmatrix.sync.aligned.m8n8.x4.trans.shared.b16 {%0,%1,%2,%3}, [%4];"
                 : "=r"(d[0]), "=r"(d[1]), "=r"(d[2]), "=r"(d[3]) : "r"(a));
}
__device__ __forceinline__ void mma16816(float* c, const uint32_t* a, uint32_t b0, uint32_t b1) {
    asm volatile(
        "mma.sync.aligned.m16n8k16.row.col.f32.bf16.bf16.f32 "
        "{%0,%1,%2,%3}, {%4,%5,%6,%7}, {%8,%9}, {%0,%1,%2,%3};"
        : "+f"(c[0]), "+f"(c[1]), "+f"(c[2]), "+f"(c[3])
        : "r"(a[0]), "r"(a[1]), "r"(a[2]), "r"(a[3]), "r"(b0), "r"(b1));
}
__device__ __forceinline__ float pick4(float4 v, int r) {
    return r == 0 ? v.x : (r == 1 ? v.y : (r == 2 ? v.z : v.w));
}

// ---------------- CSR build ----------------
__global__ void k_count(const int* __restrict__ dst, const int* __restrict__ ea) {
    int e = blockIdx.x * blockDim.x + threadIdx.x;
    if (e >= EE) return;
    atomicAdd(&g_cnt[ea[e] * NN + dst[e]], 1);
}
__global__ void k_scan() {
    __shared__ int s[1024];
    const int CH = (NN + 1023) / 1024;   // 49
    int t = threadIdx.x;
    int lo = t * CH, hi = min(lo + CH, NN);
    int sum = 0;
    for (int i = lo; i < hi; i++) {
        int tot = 0;
#pragma unroll
        for (int r = 0; r < RR; r++) {
            int c = g_cnt[r * NN + i];
            tot += c;
            g_inv[i * 4 + r] = 1.0f / (float)max(c, 1);
        }
        sum += tot;
    }
    s[t] = sum;
    __syncthreads();
    for (int d = 1; d < 1024; d <<= 1) {
        int v = (t >= d) ? s[t - d] : 0;
        __syncthreads();
        s[t] += v;
        __syncthreads();
    }
    int off = (t == 0) ? 0 : s[t - 1];
    for (int i = lo; i < hi; i++) {
        g_rowptr[i] = off;
        g_fill[i] = off;
        int tot = 0;
#pragma unroll
        for (int r = 0; r < RR; r++) tot += g_cnt[r * NN + i];
        off += tot;
    }
    if (t == 1023) g_rowptr[NN] = s[1023];
}
__global__ void k_fill(const int* __restrict__ src, const int* __restrict__ dst,
                       const int* __restrict__ ea) {
    int e = blockIdx.x * blockDim.x + threadIdx.x;
    if (e >= EE) return;
    int d = dst[e];
    int pos = atomicAdd(&g_fill[d], 1);
    g_csr[pos] = src[e] | (ea[e] << 28);
}

// ---------------- question projection: q = relu(qe @ qn_W + qn_b) ----------------
__global__ void k_q(const float* __restrict__ qe, const float* __restrict__ qnW,
                    const float* __restrict__ qnb) {
    __shared__ float sq[768];
    int g = blockIdx.x, j = threadIdx.x;
    for (int i = j; i < 768; i += 64) sq[i] = qe[g * 768 + i];
    __syncthreads();
    float acc = qnb[j];
    for (int k = 0; k < 768; k++) acc = fmaf(sq[k], qnW[k * 64 + j], acc);
    g_q[g * 64 + j] = fmaxf(acc, 0.0f);
}

// ---------------- layer-0 activation split from x ----------------
__global__ void k_prepA0(const float* __restrict__ x) {
    int idx = blockIdx.x * blockDim.x + threadIdx.x;
    if (idx >= NN * 128) return;
    int i = idx >> 7, k = idx & 127;
    float v = x[idx];
    __nv_bfloat16 hi = __float2bfloat16(v);
    float lo = v - __bfloat162float(hi);
    g_Asp[i * 256 + k]       = hi;
    g_Asp[i * 256 + 128 + k] = __float2bfloat16(lo);
}

// ---------------- q[batch] fill into layer-1 activation cols 64..127 ----------------
__global__ void k_qfill(const int* __restrict__ batch) {
    int idx = blockIdx.x * blockDim.x + threadIdx.x;
    if (idx >= NN * 32) return;
    int i = idx >> 5;
    int j = (idx & 31) * 2;
    int b = batch[i];
    float v0 = g_q[b * 64 + j], v1 = g_q[b * 64 + j + 1];
    __nv_bfloat16 h0 = __float2bfloat16(v0), h1 = __float2bfloat16(v1);
    __nv_bfloat16 l0 = __float2bfloat16(v0 - __bfloat162float(h0));
    __nv_bfloat16 l1 = __float2bfloat16(v1 - __bfloat162float(h1));
    __nv_bfloat162 hh; hh.x = h0; hh.y = h1;
    __nv_bfloat162 ll; ll.x = l0; ll.y = l1;
    *(__nv_bfloat162*)(g_Asp + (size_t)i * 256 + 64 + j)  = hh;
    *(__nv_bfloat162*)(g_Asp + (size_t)i * 256 + 192 + j) = ll;
}

// ---------------- weight concat + split: [root | W0..W3] ----------------
__global__ void k_prepB(const float* __restrict__ root, const float* __restrict__ W, int out) {
    int ncols = 5 * out;
    int idx = blockIdx.x * blockDim.x + threadIdx.x;
    if (idx >= 256 * ncols) return;
    int k2 = idx / ncols, j = idx % ncols;
    int k = k2 & 127;
    float v = (j < out) ? root[k * out + j]
                        : W[((j / out - 1) * 128 + k) * out + (j % out)];
    __nv_bfloat16 h = __float2bfloat16(v);
    if (k2 >= 128) h = __float2bfloat16(v - __bfloat162float(h));
    g_Bsp[k2 * ncols + j] = h;
}

// ---------------- GEMM: [Yself fp32 | Ymsg fp16] = Asp @ Bsp (3-term bf16 split) ----------------
#define AST 264   // 256 + 8 pad (bf16 elems)
#define BST 72    // 64 + 8 pad
#define GEMM_SMEM ((128 * AST + 256 * BST) * 2)

__global__ void __launch_bounds__(256) k_gemm(float* __restrict__ Ys,
                                              __half* __restrict__ Ym,
                                              const float* __restrict__ bias,
                                              int ncols, int out) {
    extern __shared__ __nv_bfloat16 smem[];
    __nv_bfloat16* sA = smem;                 // [128][AST]
    __nv_bfloat16* sB = smem + 128 * AST;     // [256][BST]
    int m0 = blockIdx.x * 128;
    int n0 = blockIdx.y * 64;
    int t = threadIdx.x;

#pragma unroll
    for (int v = 0; v < 16; v++) {
        int fidx = v * 256 + t;
        int row = fidx >> 5;
        int c8 = (fidx & 31) * 8;
        int grow = m0 + row;
        uint4 val = make_uint4(0, 0, 0, 0);
        if (grow < NN) val = *(const uint4*)(g_Asp + (size_t)grow * 256 + c8);
        *(uint4*)(sA + row * AST + c8) = val;
    }
#pragma unroll
    for (int v = 0; v < 8; v++) {
        int fidx = v * 256 + t;
        int row = fidx >> 3;
        int c8 = (fidx & 7) * 8;
        uint4 val = *(const uint4*)(g_Bsp + (size_t)row * ncols + n0 + c8);
        *(uint4*)(sB + row * BST + c8) = val;
    }
    __syncthreads();

    int w = t >> 5, lane = t & 31;
    int wm = (w & 3) * 32, wn = (w >> 2) * 32;
    int lr = lane & 15, lc = lane >> 4;

    float acc[2][4][4];
#pragma unroll
    for (int mt = 0; mt < 2; mt++)
#pragma unroll
        for (int nt = 0; nt < 4; nt++)
#pragma unroll
            for (int i = 0; i < 4; i++) acc[mt][nt][i] = 0.0f;

#pragma unroll
    for (int s = 0; s < 3; s++) {
        int aBase = (s == 1) ? 128 : 0;   // seg0: Ah*Bh, seg1: Al*Bh, seg2: Ah*Bl
        int bBase = (s == 2) ? 128 : 0;
#pragma unroll
        for (int kk = 0; kk < 8; kk++) {
            int ka = aBase + kk * 16;
            int kb = bBase + kk * 16;
            uint32_t a[2][4], b[2][4];
#pragma unroll
            for (int mt = 0; mt < 2; mt++)
                ldsm4(a[mt], sA + (wm + mt * 16 + lr) * AST + ka + lc * 8);
#pragma unroll
            for (int nh = 0; nh < 2; nh++)
                ldsm4t(b[nh], sB + (kb + lr) * BST + wn + nh * 16 + lc * 8);
#pragma unroll
            for (int mt = 0; mt < 2; mt++)
#pragma unroll
                for (int nt = 0; nt < 4; nt++) {
                    int nh = nt >> 1, h = (nt & 1) * 2;
                    mma16816(acc[mt][nt], a[mt], b[nh][h], b[nh][h + 1]);
                }
        }
    }

    bool isSelf = (n0 < out);
    int g = lane >> 2, tg = lane & 3;
    int pitchM = 4 * out;
#pragma unroll
    for (int mt = 0; mt < 2; mt++) {
#pragma unroll
        for (int nt = 0; nt < 4; nt++) {
            int col = n0 + wn + nt * 8 + tg * 2;
            int r0 = m0 + wm + mt * 16 + g;
            int r1 = r0 + 8;
            if (isSelf) {
                float b0 = bias[col], b1 = bias[col + 1];
                if (r0 < NN) {
                    Ys[(size_t)r0 * out + col]     = acc[mt][nt][0] + b0;
                    Ys[(size_t)r0 * out + col + 1] = acc[mt][nt][1] + b1;
                }
                if (r1 < NN) {
                    Ys[(size_t)r1 * out + col]     = acc[mt][nt][2] + b0;
                    Ys[(size_t)r1 * out + col + 1] = acc[mt][nt][3] + b1;
                }
            } else {
                int mc = col - out;
                if (r0 < NN)
                    *(__half2*)(Ym + (size_t)r0 * pitchM + mc) =
                        __floats2half2_rn(acc[mt][nt][0], acc[mt][nt][1]);
                if (r1 < NN)
                    *(__half2*)(Ym + (size_t)r1 * pitchM + mc) =
                        __floats2half2_rn(acc[mt][nt][2], acc[mt][nt][3]);
            }
        }
    }
}

// ---------------- pull aggregation: one warp per node; fused relu+split epilogue ----------------
// MODE 0: write relu(total) split to g_Asp (hi at col, lo at col+128)
// MODE 1: write total fp32 to Optr (final layer)
template <int OUT, int MODE>
__global__ void __launch_bounds__(256) k_agg(float* __restrict__ Optr) {
    int w = (blockIdx.x * 256 + threadIdx.x) >> 5;
    if (w >= NN) return;
    int lane = threadIdx.x & 31;
    constexpr int V = OUT / 32;        // 4 or 2 floats per lane
    constexpr int PITCH = 4 * OUT;     // Ymsg row pitch (halves)
    int start = g_rowptr[w], end = g_rowptr[w + 1];
    float4 iv4 = *(const float4*)(g_inv + w * 4);

    float acc[V];
    {
        const float* sp = g_Ys + (size_t)w * OUT + lane * V;
        if constexpr (V == 4) {
            float4 s = *(const float4*)sp;
            acc[0] = s.x; acc[1] = s.y; acc[2] = s.z; acc[3] = s.w;
        } else {
            float2 s = *(const float2*)sp;
            acc[0] = s.x; acc[1] = s.y;
        }
    }

    int e = start;
    for (; e + 2 <= end; e += 2) {
        int u0 = g_csr[e], u1 = g_csr[e + 1];
        int s0 = u0 & 0x0FFFFFFF, r0 = ((unsigned)u0) >> 28;
        int s1 = u1 & 0x0FFFFFFF, r1 = ((unsigned)u1) >> 28;
        const __half* p0 = g_Ym + (size_t)s0 * PITCH + r0 * OUT + lane * V;
        const __half* p1 = g_Ym + (size_t)s1 * PITCH + r1 * OUT + lane * V;
        float i0 = pick4(iv4, r0), i1 = pick4(iv4, r1);
        if constexpr (V == 4) {
            uint2 w0 = *(const uint2*)p0;
            uint2 w1 = *(const uint2*)p1;
            float2 a0 = __half22float2(*(__half2*)&w0.x);
            float2 a1 = __half22float2(*(__half2*)&w0.y);
            float2 b0 = __half22float2(*(__half2*)&w1.x);
            float2 b1 = __half22float2(*(__half2*)&w1.y);
            acc[0] += a0.x * i0; acc[1] += a0.y * i0;
            acc[2] += a1.x * i0; acc[3] += a1.y * i0;
            acc[0] += b0.x * i1; acc[1] += b0.y * i1;
            acc[2] += b1.x * i1; acc[3] += b1.y * i1;
        } else {
            uint32_t w0 = *(const uint32_t*)p0;
            uint32_t w1 = *(const uint32_t*)p1;
            float2 a0 = __half22float2(*(__half2*)&w0);
            float2 b0 = __half22float2(*(__half2*)&w1);
            acc[0] += a0.x * i0; acc[1] += a0.y * i0;
            acc[0] += b0.x * i1; acc[1] += b0.y * i1;
        }
    }
    if (e < end) {
        int u0 = g_csr[e];
        int s0 = u0 & 0x0FFFFFFF, r0 = ((unsigned)u0) >> 28;
        const __half* p0 = g_Ym + (size_t)s0 * PITCH + r0 * OUT + lane * V;
        float i0 = pick4(iv4, r0);
        if constexpr (V == 4) {
            uint2 w0 = *(const uint2*)p0;
            float2 a0 = __half22float2(*(__half2*)&w0.x);
            float2 a1 = __half22float2(*(__half2*)&w0.y);
            acc[0] += a0.x * i0; acc[1] += a0.y * i0;
            acc[2] += a1.x * i0; acc[3] += a1.y * i0;
        } else {
            uint32_t w0 = *(const uint32_t*)p0;
            float2 a0 = __half22float2(*(__half2*)&w0);
            acc[0] += a0.x * i0; acc[1] += a0.y * i0;
        }
    }

    if constexpr (MODE == 0) {
        union { __nv_bfloat16 h[V]; uint2 u2; uint32_t u1; } ph, pl;
#pragma unroll
        for (int j = 0; j < V; j++) {
            float v = fmaxf(acc[j], 0.0f);
            __nv_bfloat16 hi = __float2bfloat16(v);
            ph.h[j] = hi;
            pl.h[j] = __float2bfloat16(v - __bfloat162float(hi));
        }
        __nv_bfloat16* base = g_Asp + (size_t)w * 256 + lane * V;
        if constexpr (V == 4) {
            *(uint2*)base         = ph.u2;
            *(uint2*)(base + 128) = pl.u2;
        } else {
            *(uint32_t*)base         = ph.u1;
            *(uint32_t*)(base + 128) = pl.u1;
        }
    } else {
        float* op = Optr + (size_t)w * OUT + lane * V;
        if constexpr (V == 4) {
            float4 r; r.x = acc[0]; r.y = acc[1]; r.z = acc[2]; r.w = acc[3];
            *(float4*)op = r;
        } else {
            float2 r; r.x = acc[0]; r.y = acc[1];
            *(float2*)op = r;
        }
    }
}

// ---------------- host orchestration ----------------
extern "C" void kernel_launch(void* const* d_in, const int* in_sizes, int n_in,
                              void* d_out, int out_size) {
    const float* x     = (const float*)d_in[0];
    const int*   ei    = (const int*)d_in[1];
    const int*   ea    = (const int*)d_in[2];
    const int*   batch = (const int*)d_in[3];
    const float* qe    = (const float*)d_in[4];
    const float* qnW   = (const float*)d_in[5];
    const float* qnb   = (const float*)d_in[6];
    const float* W0 = (const float*)d_in[7],  *root0 = (const float*)d_in[8],  *b0 = (const float*)d_in[9];
    const float* W1 = (const float*)d_in[10], *root1 = (const float*)d_in[11], *b1 = (const float*)d_in[12];
    const float* W2 = (const float*)d_in[13], *root2 = (const float*)d_in[14], *b2 = (const float*)d_in[15];
    const float* W3 = (const float*)d_in[16], *root3 = (const float*)d_in[17], *b3 = (const float*)d_in[18];
    float* out = (float*)d_out;

    const int* src = ei;
    const int* dst = ei + EE;

    float*  Ys; cudaGetSymbolAddress((void**)&Ys, g_Ys);
    __half* Ym; cudaGetSymbolAddress((void**)&Ym, g_Ym);
    int*    cnt; cudaGetSymbolAddress((void**)&cnt, g_cnt);

    cudaFuncSetAttribute(k_gemm, cudaFuncAttributeMaxDynamicSharedMemorySize, GEMM_SMEM);

    const int MG = 391;                       // ceil(50000/128)
    const int AGG_G = (NN * 32 + 255) / 256;  // 6250

    cudaMemsetAsync(cnt, 0, RR * NN * sizeof(int));

    // Front-load GEMM0 prerequisites so ncu -s 5 catches k_gemm.
    k_prepA0<<<(NN * 128 + 255) / 256, 256>>>(x);                 // launch 1
    k_prepB<<<(256 * 320 + 255) / 256, 256>>>(root0, W0, 64);     // launch 2
    k_q<<<GG, 64>>>(qe, qnW, qnb);                                // launch 3
    k_count<<<(EE + 255) / 256, 256>>>(dst, ea);                  // launch 4
    k_gemm<<<dim3(MG, 5), 256, GEMM_SMEM>>>(Ys, Ym, b0, 320, 64); // launch 5 (profiled)
    k_scan<<<1, 1024>>>();                                        // launch 6
    k_fill<<<(EE + 255) / 256, 256>>>(src, dst, ea);              // launch 7

    // Layer 0 aggregation -> Asp cols [0:64)+[128:192); q fills [64:128)+[192:256)
    k_agg<64, 0><<<AGG_G, 256>>>(nullptr);
    k_qfill<<<(NN * 32 + 255) / 256, 256>>>(batch);

    // Layer 1: in=128, out=128
    k_prepB<<<(256 * 640 + 255) / 256, 256>>>(root1, W1, 128);
    k_gemm<<<dim3(MG, 10), 256, GEMM_SMEM>>>(Ys, Ym, b1, 640, 128);
    k_agg<128, 0><<<AGG_G, 256>>>(nullptr);

    // Layer 2: in=128, out=128
    k_prepB<<<(256 * 640 + 255) / 256, 256>>>(root2, W2, 128);
    k_gemm<<<dim3(MG, 10), 256, GEMM_SMEM>>>(Ys, Ym, b2, 640, 128);
    k_agg<128, 0><<<AGG_G, 256>>>(nullptr);

    // Layer 3: in=128, out=64 -> d_out
    k_prepB<<<(256 * 320 + 255) / 256, 256>>>(root3, W3, 64);
    k_gemm<<<dim3(MG, 5), 256, GEMM_SMEM>>>(Ys, Ym, b3, 320, 64);
    k_agg<64, 1><<<AGG_G, 256>>>(out);
}

// round 4
// speedup vs baseline: 2.4830x; 2.1202x over previous
#include <cuda_runtime.h>
#include <cuda_bf16.h>
#include <cuda_fp16.h>
#include <cstdint>

#define NN 50000
#define EE 800000
#define RR 4
#define GG 16

// ---------------- scratch (device globals; no allocation) ----------------
__device__ float   g_Ys[NN * 128];          // self+bias, fp32 [N][out]
__device__ __half  g_Ym[NN * 512];          // messages fp16 [N][4*out] (L2-resident)
__device__ __half  g_Asp[NN * 256];         // split activations [N][Ah(128)|Al(128)] fp16
__device__ __half  g_Bsp[128 * 640];        // weights fp16, row-major [k][5*out]
__device__ float   g_q[GG * 64];
__device__ int     g_cnt[RR * NN];
__device__ float   g_inv[NN * 4];
__device__ int     g_deg[NN];
__device__ int     g_part[256];
__device__ int     g_rowptr[NN + 1];
__device__ int     g_fill[NN];
__device__ int     g_csr[EE];               // src | (rel<<28)

// ---------------- helpers ----------------
__device__ __forceinline__ uint32_t smem_u32(const void* p) {
    return (uint32_t)__cvta_generic_to_shared(p);
}
__device__ __forceinline__ void ldsm4(uint32_t* d, const __half* p) {
    uint32_t a = smem_u32(p);
    asm volatile("ldmatrix.sync.aligned.m8n8.x4.shared.b16 {%0,%1,%2,%3}, [%4];"
                 : "=r"(d[0]), "=r"(d[1]), "=r"(d[2]), "=r"(d[3]) : "r"(a));
}
__device__ __forceinline__ void ldsm4t(uint32_t* d, const __half* p) {
    uint32_t a = smem_u32(p);
    asm volatile("ldmatrix.sync.aligned.m8n8.x4.trans.shared.b16 {%0,%1,%2,%3}, [%4];"
                 : "=r"(d[0]), "=r"(d[1]), "=r"(d[2]), "=r"(d[3]) : "r"(a));
}
__device__ __forceinline__ void mma16816(float* c, const uint32_t* a, uint32_t b0, uint32_t b1) {
    asm volatile(
        "mma.sync.aligned.m16n8k16.row.col.f32.f16.f16.f32 "
        "{%0,%1,%2,%3}, {%4,%5,%6,%7}, {%8,%9}, {%0,%1,%2,%3};"
        : "+f"(c[0]), "+f"(c[1]), "+f"(c[2]), "+f"(c[3])
        : "r"(a[0]), "r"(a[1]), "r"(a[2]), "r"(a[3]), "r"(b0), "r"(b1));
}
__device__ __forceinline__ float pick4(float4 v, int r) {
    return r == 0 ? v.x : (r == 1 ? v.y : (r == 2 ? v.z : v.w));
}

// ---------------- layer-0 activation split from x (+ zero g_cnt) ----------------
__global__ void k_prepA0(const float* __restrict__ x) {
    int idx = blockIdx.x * blockDim.x + threadIdx.x;
    if (idx < RR * NN) g_cnt[idx] = 0;
    if (idx >= NN * 128) return;
    int i = idx >> 7, k = idx & 127;
    float v = x[idx];
    __half hi = __float2half_rn(v);
    float lo = v - __half2float(hi);
    g_Asp[i * 256 + k]       = hi;
    g_Asp[i * 256 + 128 + k] = __float2half_rn(lo);
}

// ---------------- weight concat fp16: B[k][5*out] ----------------
__global__ void k_prepB(const float* __restrict__ root, const float* __restrict__ W, int out) {
    int ncols = 5 * out;
    int idx = blockIdx.x * blockDim.x + threadIdx.x;
    if (idx >= 128 * ncols) return;
    int k = idx / ncols, j = idx % ncols;
    float v = (j < out) ? root[k * out + j]
                        : W[((j / out - 1) * 128 + k) * out + (j % out)];
    g_Bsp[idx] = __float2half_rn(v);
}

// ---------------- question projection ----------------
__global__ void k_q(const float* __restrict__ qe, const float* __restrict__ qnW,
                    const float* __restrict__ qnb) {
    __shared__ float sq[768];
    int g = blockIdx.x, j = threadIdx.x;
    for (int i = j; i < 768; i += 64) sq[i] = qe[g * 768 + i];
    __syncthreads();
    float acc = qnb[j];
    for (int k = 0; k < 768; k++) acc = fmaf(sq[k], qnW[k * 64 + j], acc);
    g_q[g * 64 + j] = fmaxf(acc, 0.0f);
}

// ---------------- CSR build ----------------
__global__ void k_count(const int* __restrict__ dst, const int* __restrict__ ea) {
    int e = blockIdx.x * blockDim.x + threadIdx.x;
    if (e >= EE) return;
    atomicAdd(&g_cnt[ea[e] * NN + dst[e]], 1);
}
__global__ void k_scan1() {
    int t = threadIdx.x;
    int i = blockIdx.x * 256 + t;
    int tot = 0;
    if (i < NN) {
#pragma unroll
        for (int r = 0; r < RR; r++) {
            int c = g_cnt[r * NN + i];
            tot += c;
            g_inv[i * 4 + r] = 1.0f / (float)max(c, 1);
        }
        g_deg[i] = tot;
    }
    __shared__ int s[256];
    s[t] = tot;
    __syncthreads();
    for (int d = 128; d; d >>= 1) {
        if (t < d) s[t] += s[t + d];
        __syncthreads();
    }
    if (t == 0) g_part[blockIdx.x] = s[0];
}
__global__ void k_scan2() {
    __shared__ int s[256];
    int t = threadIdx.x;
    int v = (t < 196) ? g_part[t] : 0;
    s[t] = v;
    __syncthreads();
    for (int d = 1; d < 256; d <<= 1) {
        int x = (t >= d) ? s[t - d] : 0;
        __syncthreads();
        s[t] += x;
        __syncthreads();
    }
    if (t < 196) g_part[t] = s[t] - v;
    if (t == 255) g_rowptr[NN] = s[255];
}
__global__ void k_scan3() {
    int t = threadIdx.x;
    int i = blockIdx.x * 256 + t;
    int v = (i < NN) ? g_deg[i] : 0;
    __shared__ int s[256];
    s[t] = v;
    __syncthreads();
    for (int d = 1; d < 256; d <<= 1) {
        int x = (t >= d) ? s[t - d] : 0;
        __syncthreads();
        s[t] += x;
        __syncthreads();
    }
    if (i < NN) {
        int off = g_part[blockIdx.x] + s[t] - v;
        g_rowptr[i] = off;
        g_fill[i] = off;
    }
}
__global__ void k_fill(const int* __restrict__ src, const int* __restrict__ dst,
                       const int* __restrict__ ea) {
    int e = blockIdx.x * blockDim.x + threadIdx.x;
    if (e >= EE) return;
    int d = dst[e];
    int pos = atomicAdd(&g_fill[d], 1);
    g_csr[pos] = src[e] | (ea[e] << 28);
}

// ---------------- q[batch] fill into layer-1 activation cols 64..127 ----------------
__global__ void k_qfill(const int* __restrict__ batch) {
    int idx = blockIdx.x * blockDim.x + threadIdx.x;
    if (idx >= NN * 32) return;
    int i = idx >> 5;
    int j = (idx & 31) * 2;
    int b = batch[i];
    float v0 = g_q[b * 64 + j], v1 = g_q[b * 64 + j + 1];
    __half h0 = __float2half_rn(v0), h1 = __float2half_rn(v1);
    __half l0 = __float2half_rn(v0 - __half2float(h0));
    __half l1 = __float2half_rn(v1 - __half2float(h1));
    __half2 hh; hh.x = h0; hh.y = h1;
    __half2 ll; ll.x = l0; ll.y = l1;
    *(__half2*)(g_Asp + (size_t)i * 256 + 64 + j)  = hh;
    *(__half2*)(g_Asp + (size_t)i * 256 + 192 + j) = ll;
}

// ---------------- GEMM: per-CTA 128 rows, loop over N-blocks; fp16 2-term split ----------------
#define AST 264   // 256 + 8 pad (halves)
#define BST 72    // 64 + 8 pad
#define GEMM_SMEM ((128 * AST + 128 * BST) * 2)

__global__ void __launch_bounds__(256) k_gemm(const float* __restrict__ bias,
                                              int out, int nblocks) {
    extern __shared__ __half smem[];
    __half* sA = smem;                 // [128][AST]
    __half* sB = smem + 128 * AST;     // [128][BST]
    int m0 = blockIdx.x * 128;
    int t = threadIdx.x;
    int ncols = 5 * out;

    // load A tile (128 x 256 halves = 4096 uint4)
#pragma unroll
    for (int i = 0; i < 16; i++) {
        int idx = t + i * 256;
        int row = idx >> 5;
        int c8 = (idx & 31) * 8;
        int grow = m0 + row;
        uint4 val = make_uint4(0, 0, 0, 0);
        if (grow < NN) val = *(const uint4*)(g_Asp + (size_t)grow * 256 + c8);
        *(uint4*)(sA + row * AST + c8) = val;
    }

    int w = t >> 5, lane = t & 31;
    int wm = (w & 3) * 32, wn = (w >> 2) * 32;
    int lr = lane & 15, lc = lane >> 4;
    int g = lane >> 2, tg = lane & 3;
    int pitchM = 4 * out;

    for (int nb = 0; nb < nblocks; nb++) {
        int n0 = nb * 64;
        // load B tile (128 x 64 halves = 1024 uint4)
#pragma unroll
        for (int i = 0; i < 4; i++) {
            int idx = t + i * 256;
            int row = idx >> 3;
            int c8 = (idx & 7) * 8;
            uint4 val = *(const uint4*)(g_Bsp + (size_t)row * ncols + n0 + c8);
            *(uint4*)(sB + row * BST + c8) = val;
        }
        __syncthreads();

        float acc[2][4][4];
#pragma unroll
        for (int mt = 0; mt < 2; mt++)
#pragma unroll
            for (int nt = 0; nt < 4; nt++)
#pragma unroll
                for (int i = 0; i < 4; i++) acc[mt][nt][i] = 0.0f;

#pragma unroll
        for (int kk = 0; kk < 8; kk++) {
            uint32_t b[2][4];
#pragma unroll
            for (int nh = 0; nh < 2; nh++)
                ldsm4t(b[nh], sB + (kk * 16 + lr) * BST + wn + nh * 16 + lc * 8);
#pragma unroll
            for (int seg = 0; seg < 2; seg++) {
                uint32_t a[2][4];
#pragma unroll
                for (int mt = 0; mt < 2; mt++)
                    ldsm4(a[mt], sA + (wm + mt * 16 + lr) * AST + seg * 128 + kk * 16 + lc * 8);
#pragma unroll
                for (int mt = 0; mt < 2; mt++)
#pragma unroll
                    for (int nt = 0; nt < 4; nt++) {
                        int nh = nt >> 1, h = (nt & 1) * 2;
                        mma16816(acc[mt][nt], a[mt], b[nh][h], b[nh][h + 1]);
                    }
            }
        }

        bool isSelf = (n0 < out);
#pragma unroll
        for (int mt = 0; mt < 2; mt++) {
#pragma unroll
            for (int nt = 0; nt < 4; nt++) {
                int col = n0 + wn + nt * 8 + tg * 2;
                int r0 = m0 + wm + mt * 16 + g;
                int r1 = r0 + 8;
                if (isSelf) {
                    float b0 = bias[col], b1 = bias[col + 1];
                    if (r0 < NN) {
                        g_Ys[(size_t)r0 * out + col]     = acc[mt][nt][0] + b0;
                        g_Ys[(size_t)r0 * out + col + 1] = acc[mt][nt][1] + b1;
                    }
                    if (r1 < NN) {
                        g_Ys[(size_t)r1 * out + col]     = acc[mt][nt][2] + b0;
                        g_Ys[(size_t)r1 * out + col + 1] = acc[mt][nt][3] + b1;
                    }
                } else {
                    int mc = col - out;
                    if (r0 < NN)
                        *(__half2*)(g_Ym + (size_t)r0 * pitchM + mc) =
                            __floats2half2_rn(acc[mt][nt][0], acc[mt][nt][1]);
                    if (r1 < NN)
                        *(__half2*)(g_Ym + (size_t)r1 * pitchM + mc) =
                            __floats2half2_rn(acc[mt][nt][2], acc[mt][nt][3]);
                }
            }
        }
        __syncthreads();
    }
}

// ---------------- pull aggregation: one warp per node; fused relu+split epilogue ----------------
template <int OUT, int MODE>
__global__ void __launch_bounds__(256) k_agg(float* __restrict__ Optr) {
    int w = (blockIdx.x * 256 + threadIdx.x) >> 5;
    if (w >= NN) return;
    int lane = threadIdx.x & 31;
    constexpr int V = OUT / 32;
    constexpr int PITCH = 4 * OUT;
    int start = g_rowptr[w], end = g_rowptr[w + 1];
    float4 iv4 = *(const float4*)(g_inv + w * 4);

    float acc[V];
    {
        const float* sp = g_Ys + (size_t)w * OUT + lane * V;
        if constexpr (V == 4) {
            float4 s = *(const float4*)sp;
            acc[0] = s.x; acc[1] = s.y; acc[2] = s.z; acc[3] = s.w;
        } else {
            float2 s = *(const float2*)sp;
            acc[0] = s.x; acc[1] = s.y;
        }
    }

    int e = start;
    for (; e + 2 <= end; e += 2) {
        int u0 = g_csr[e], u1 = g_csr[e + 1];
        int s0 = u0 & 0x0FFFFFFF, r0 = ((unsigned)u0) >> 28;
        int s1 = u1 & 0x0FFFFFFF, r1 = ((unsigned)u1) >> 28;
        const __half* p0 = g_Ym + (size_t)s0 * PITCH + r0 * OUT + lane * V;
        const __half* p1 = g_Ym + (size_t)s1 * PITCH + r1 * OUT + lane * V;
        float i0 = pick4(iv4, r0), i1 = pick4(iv4, r1);
        if constexpr (V == 4) {
            uint2 w0 = *(const uint2*)p0;
            uint2 w1 = *(const uint2*)p1;
            float2 a0 = __half22float2(*(__half2*)&w0.x);
            float2 a1 = __half22float2(*(__half2*)&w0.y);
            float2 b0 = __half22float2(*(__half2*)&w1.x);
            float2 b1 = __half22float2(*(__half2*)&w1.y);
            acc[0] += a0.x * i0; acc[1] += a0.y * i0;
            acc[2] += a1.x * i0; acc[3] += a1.y * i0;
            acc[0] += b0.x * i1; acc[1] += b0.y * i1;
            acc[2] += b1.x * i1; acc[3] += b1.y * i1;
        } else {
            uint32_t w0 = *(const uint32_t*)p0;
            uint32_t w1 = *(const uint32_t*)p1;
            float2 a0 = __half22float2(*(__half2*)&w0);
            float2 b0 = __half22float2(*(__half2*)&w1);
            acc[0] += a0.x * i0; acc[1] += a0.y * i0;
            acc[0] += b0.x * i1; acc[1] += b0.y * i1;
        }
    }
    if (e < end) {
        int u0 = g_csr[e];
        int s0 = u0 & 0x0FFFFFFF, r0 = ((unsigned)u0) >> 28;
        const __half* p0 = g_Ym + (size_t)s0 * PITCH + r0 * OUT + lane * V;
        float i0 = pick4(iv4, r0);
        if constexpr (V == 4) {
            uint2 w0 = *(const uint2*)p0;
            float2 a0 = __half22float2(*(__half2*)&w0.x);
            float2 a1 = __half22float2(*(__half2*)&w0.y);
            acc[0] += a0.x * i0; acc[1] += a0.y * i0;
            acc[2] += a1.x * i0; acc[3] += a1.y * i0;
        } else {
            uint32_t w0 = *(const uint32_t*)p0;
            float2 a0 = __half22float2(*(__half2*)&w0);
            acc[0] += a0.x * i0; acc[1] += a0.y * i0;
        }
    }

    if constexpr (MODE == 0) {
        union { __half h[V]; uint2 u2; uint32_t u1; } ph, pl;
#pragma unroll
        for (int j = 0; j < V; j++) {
            float v = fmaxf(acc[j], 0.0f);
            __half hi = __float2half_rn(v);
            ph.h[j] = hi;
            pl.h[j] = __float2half_rn(v - __half2float(hi));
        }
        __half* base = g_Asp + (size_t)w * 256 + lane * V;
        if constexpr (V == 4) {
            *(uint2*)base         = ph.u2;
            *(uint2*)(base + 128) = pl.u2;
        } else {
            *(uint32_t*)base         = ph.u1;
            *(uint32_t*)(base + 128) = pl.u1;
        }
    } else {
        float* op = Optr + (size_t)w * OUT + lane * V;
        if constexpr (V == 4) {
            float4 r; r.x = acc[0]; r.y = acc[1]; r.z = acc[2]; r.w = acc[3];
            *(float4*)op = r;
        } else {
            float2 r; r.x = acc[0]; r.y = acc[1];
            *(float2*)op = r;
        }
    }
}

// ---------------- host orchestration ----------------
extern "C" void kernel_launch(void* const* d_in, const int* in_sizes, int n_in,
                              void* d_out, int out_size) {
    const float* x     = (const float*)d_in[0];
    const int*   ei    = (const int*)d_in[1];
    const int*   ea    = (const int*)d_in[2];
    const int*   batch = (const int*)d_in[3];
    const float* qe    = (const float*)d_in[4];
    const float* qnW   = (const float*)d_in[5];
    const float* qnb   = (const float*)d_in[6];
    const float* W0 = (const float*)d_in[7],  *root0 = (const float*)d_in[8],  *b0 = (const float*)d_in[9];
    const float* W1 = (const float*)d_in[10], *root1 = (const float*)d_in[11], *b1 = (const float*)d_in[12];
    const float* W2 = (const float*)d_in[13], *root2 = (const float*)d_in[14], *b2 = (const float*)d_in[15];
    const float* W3 = (const float*)d_in[16], *root3 = (const float*)d_in[17], *b3 = (const float*)d_in[18];
    float* out = (float*)d_out;

    const int* src = ei;
    const int* dst = ei + EE;

    cudaFuncSetAttribute(k_gemm, cudaFuncAttributeMaxDynamicSharedMemorySize, GEMM_SMEM);

    const int MG = 391;                       // ceil(50000/128)
    const int AGG_G = (NN * 32 + 255) / 256;  // 6250

    // k_gemm is launch #4 so ncu -s captures it.
    k_prepA0<<<(NN * 128 + 255) / 256, 256>>>(x);              // 1 (also zeroes g_cnt)
    k_prepB<<<(128 * 320 + 255) / 256, 256>>>(root0, W0, 64);  // 2
    k_q<<<GG, 64>>>(qe, qnW, qnb);                             // 3
    k_gemm<<<MG, 256, GEMM_SMEM>>>(b0, 64, 5);                 // 4 (profiled)
    k_count<<<(EE + 255) / 256, 256>>>(dst, ea);               // 5
    k_scan1<<<196, 256>>>();                                   // 6
    k_scan2<<<1, 256>>>();                                     // 7
    k_scan3<<<196, 256>>>();                                   // 8
    k_fill<<<(EE + 255) / 256, 256>>>(src, dst, ea);           // 9

    k_agg<64, 0><<<AGG_G, 256>>>(nullptr);
    k_qfill<<<(NN * 32 + 255) / 256, 256>>>(batch);

    // Layer 1: in=128, out=128
    k_prepB<<<(128 * 640 + 255) / 256, 256>>>(root1, W1, 128);
    k_gemm<<<MG, 256, GEMM_SMEM>>>(b1, 128, 10);
    k_agg<128, 0><<<AGG_G, 256>>>(nullptr);

    // Layer 2: in=128, out=128
    k_prepB<<<(128 * 640 + 255) / 256, 256>>>(root2, W2, 128);
    k_gemm<<<MG, 256, GEMM_SMEM>>>(b2, 128, 10);
    k_agg<128, 0><<<AGG_G, 256>>>(nullptr);

    // Layer 3: in=128, out=64 -> d_out
    k_prepB<<<(128 * 320 + 255) / 256, 256>>>(root3, W3, 64);
    k_gemm<<<MG, 256, GEMM_SMEM>>>(b3, 64, 5);
    k_agg<64, 1><<<AGG_G, 256>>>(out);
}

// round 5
// speedup vs baseline: 2.5141x; 1.0125x over previous
#include <cuda_runtime.h>
#include <cuda_bf16.h>
#include <cuda_fp16.h>
#include <cstdint>

#define NN 50000
#define EE 800000
#define RR 4
#define GG 16

// ---------------- scratch (device globals; no allocation) ----------------
__device__ float   g_Ys[NN * 128];          // self+bias, fp32 [N][out]
__device__ __half  g_Ym[NN * 512];          // messages fp16 [N][4*out] (L2-resident)
__device__ __half  g_Asp[NN * 256];         // split activations [N][Ah(128)|Al(128)] fp16
__device__ __half  g_Bsp[128 * 640];        // weights fp16, row-major [k][5*out]
__device__ float   g_q[GG * 64];
__device__ int     g_cnt[RR * NN];
__device__ float   g_inv[NN * 4];
__device__ int     g_deg[NN];
__device__ int     g_part[256];
__device__ int     g_rowptr[NN + 1];
__device__ int     g_fill[NN];
__device__ int     g_csr[EE];               // src | (rel<<28)

// ---------------- helpers ----------------
__device__ __forceinline__ uint32_t smem_u32(const void* p) {
    return (uint32_t)__cvta_generic_to_shared(p);
}
__device__ __forceinline__ void ldsm4(uint32_t* d, const __half* p) {
    uint32_t a = smem_u32(p);
    asm volatile("ldmatrix.sync.aligned.m8n8.x4.shared.b16 {%0,%1,%2,%3}, [%4];"
                 : "=r"(d[0]), "=r"(d[1]), "=r"(d[2]), "=r"(d[3]) : "r"(a));
}
__device__ __forceinline__ void ldsm4t(uint32_t* d, const __half* p) {
    uint32_t a = smem_u32(p);
    asm volatile("ldmatrix.sync.aligned.m8n8.x4.trans.shared.b16 {%0,%1,%2,%3}, [%4];"
                 : "=r"(d[0]), "=r"(d[1]), "=r"(d[2]), "=r"(d[3]) : "r"(a));
}
__device__ __forceinline__ void mma16816(float* c, const uint32_t* a, uint32_t b0, uint32_t b1) {
    asm volatile(
        "mma.sync.aligned.m16n8k16.row.col.f32.f16.f16.f32 "
        "{%0,%1,%2,%3}, {%4,%5,%6,%7}, {%8,%9}, {%0,%1,%2,%3};"
        : "+f"(c[0]), "+f"(c[1]), "+f"(c[2]), "+f"(c[3])
        : "r"(a[0]), "r"(a[1]), "r"(a[2]), "r"(a[3]), "r"(b0), "r"(b1));
}
__device__ __forceinline__ void cp_async16(uint32_t smem_addr, const void* gptr) {
    asm volatile("cp.async.cg.shared.global [%0], [%1], 16;" :: "r"(smem_addr), "l"(gptr));
}
__device__ __forceinline__ void cp_commit() {
    asm volatile("cp.async.commit_group;" ::: "memory");
}
__device__ __forceinline__ void cp_wait0() {
    asm volatile("cp.async.wait_group 0;" ::: "memory");
}
__device__ __forceinline__ float pick4(float4 v, int r) {
    return r == 0 ? v.x : (r == 1 ? v.y : (r == 2 ? v.z : v.w));
}

// ---------------- layer-0 activation split from x (+ zero g_cnt) ----------------
__global__ void k_prepA0(const float* __restrict__ x) {
    int idx = blockIdx.x * blockDim.x + threadIdx.x;
    if (idx < RR * NN) g_cnt[idx] = 0;
    if (idx >= NN * 128) return;
    int i = idx >> 7, k = idx & 127;
    float v = x[idx];
    __half hi = __float2half_rn(v);
    float lo = v - __half2float(hi);
    g_Asp[i * 256 + k]       = hi;
    g_Asp[i * 256 + 128 + k] = __float2half_rn(lo);
}

// ---------------- weight concat fp16: B[k][5*out] ----------------
__global__ void k_prepB(const float* __restrict__ root, const float* __restrict__ W, int out) {
    int ncols = 5 * out;
    int idx = blockIdx.x * blockDim.x + threadIdx.x;
    if (idx >= 128 * ncols) return;
    int k = idx / ncols, j = idx % ncols;
    float v = (j < out) ? root[k * out + j]
                        : W[((j / out - 1) * 128 + k) * out + (j % out)];
    g_Bsp[idx] = __float2half_rn(v);
}

// ---------------- question projection ----------------
__global__ void k_q(const float* __restrict__ qe, const float* __restrict__ qnW,
                    const float* __restrict__ qnb) {
    __shared__ float sq[768];
    int g = blockIdx.x, j = threadIdx.x;
    for (int i = j; i < 768; i += 64) sq[i] = qe[g * 768 + i];
    __syncthreads();
    float acc = qnb[j];
    for (int k = 0; k < 768; k++) acc = fmaf(sq[k], qnW[k * 64 + j], acc);
    g_q[g * 64 + j] = fmaxf(acc, 0.0f);
}

// ---------------- CSR build ----------------
__global__ void k_count(const int* __restrict__ dst, const int* __restrict__ ea) {
    int e = blockIdx.x * blockDim.x + threadIdx.x;
    if (e >= EE) return;
    atomicAdd(&g_cnt[ea[e] * NN + dst[e]], 1);
}
__global__ void k_scan1() {
    int t = threadIdx.x;
    int i = blockIdx.x * 256 + t;
    int tot = 0;
    if (i < NN) {
#pragma unroll
        for (int r = 0; r < RR; r++) {
            int c = g_cnt[r * NN + i];
            tot += c;
            g_inv[i * 4 + r] = 1.0f / (float)max(c, 1);
        }
        g_deg[i] = tot;
    }
    __shared__ int s[256];
    s[t] = tot;
    __syncthreads();
    for (int d = 128; d; d >>= 1) {
        if (t < d) s[t] += s[t + d];
        __syncthreads();
    }
    if (t == 0) g_part[blockIdx.x] = s[0];
}
__global__ void k_scan2() {
    __shared__ int s[256];
    int t = threadIdx.x;
    int v = (t < 196) ? g_part[t] : 0;
    s[t] = v;
    __syncthreads();
    for (int d = 1; d < 256; d <<= 1) {
        int x = (t >= d) ? s[t - d] : 0;
        __syncthreads();
        s[t] += x;
        __syncthreads();
    }
    if (t < 196) g_part[t] = s[t] - v;
    if (t == 255) g_rowptr[NN] = s[255];
}
__global__ void k_scan3() {
    int t = threadIdx.x;
    int i = blockIdx.x * 256 + t;
    int v = (i < NN) ? g_deg[i] : 0;
    __shared__ int s[256];
    s[t] = v;
    __syncthreads();
    for (int d = 1; d < 256; d <<= 1) {
        int x = (t >= d) ? s[t - d] : 0;
        __syncthreads();
        s[t] += x;
        __syncthreads();
    }
    if (i < NN) {
        int off = g_part[blockIdx.x] + s[t] - v;
        g_rowptr[i] = off;
        g_fill[i] = off;
    }
}
__global__ void k_fill(const int* __restrict__ src, const int* __restrict__ dst,
                       const int* __restrict__ ea) {
    int e = blockIdx.x * blockDim.x + threadIdx.x;
    if (e >= EE) return;
    int d = dst[e];
    int pos = atomicAdd(&g_fill[d], 1);
    g_csr[pos] = src[e] | (ea[e] << 28);
}

// ---------------- GEMM: 128 thr, warp tile 64x32, cp.async double-buffered B ----------------
#define AST 264   // 256 + 8 pad (halves)
#define BST 72    // 64 + 8 pad
#define GEMM_SMEM ((128 * AST + 2 * 128 * BST) * 2)

__global__ void __launch_bounds__(128) k_gemm(const float* __restrict__ bias,
                                              int out, int nblocks) {
    extern __shared__ __half smem[];
    __half* sA = smem;                        // [128][AST]
    __half* sB0 = smem + 128 * AST;           // [128][BST] x2
    int m0 = blockIdx.x * 128;
    int t = threadIdx.x;
    int ncols = 5 * out;

    // load A tile (128 x 256 halves = 4096 uint4, 32 per thread)
#pragma unroll
    for (int i = 0; i < 32; i++) {
        int idx = t + i * 128;
        int row = idx >> 5;
        int c8 = (idx & 31) * 8;
        int grow = m0 + row;
        uint4 val = make_uint4(0, 0, 0, 0);
        if (grow < NN) val = *(const uint4*)(g_Asp + (size_t)grow * 256 + c8);
        *(uint4*)(sA + row * AST + c8) = val;
    }

    // prefetch B block 0 (1024 uint4, 8 per thread)
    {
        uint32_t sbb = smem_u32(sB0);
#pragma unroll
        for (int i = 0; i < 8; i++) {
            int idx = t + i * 128;
            int row = idx >> 3;
            int c8 = (idx & 7) * 8;
            cp_async16(sbb + (row * BST + c8) * 2, g_Bsp + (size_t)row * ncols + c8);
        }
        cp_commit();
    }

    int w = t >> 5, lane = t & 31;
    int wm = (w & 1) * 64, wn = (w >> 1) * 32;
    int lr = lane & 15, lc = lane >> 4;
    int g = lane >> 2, tg = lane & 3;
    int pitchM = 4 * out;

    for (int nb = 0; nb < nblocks; nb++) {
        int n0 = nb * 64;
        __half* sB = sB0 + (nb & 1) * 128 * BST;
        cp_wait0();
        __syncthreads();   // B(nb) visible; everyone done reading B(nb-1)'s buffer

        if (nb + 1 < nblocks) {
            __half* sBn = sB0 + ((nb + 1) & 1) * 128 * BST;
            uint32_t sbb = smem_u32(sBn);
            int n1 = n0 + 64;
#pragma unroll
            for (int i = 0; i < 8; i++) {
                int idx = t + i * 128;
                int row = idx >> 3;
                int c8 = (idx & 7) * 8;
                cp_async16(sbb + (row * BST + c8) * 2, g_Bsp + (size_t)row * ncols + n1 + c8);
            }
            cp_commit();
        }

        float acc[4][4][4];
#pragma unroll
        for (int mt = 0; mt < 4; mt++)
#pragma unroll
            for (int nt = 0; nt < 4; nt++)
#pragma unroll
                for (int i = 0; i < 4; i++) acc[mt][nt][i] = 0.0f;

#pragma unroll
        for (int kk = 0; kk < 8; kk++) {
            uint32_t b[2][4];
#pragma unroll
            for (int nh = 0; nh < 2; nh++)
                ldsm4t(b[nh], sB + (kk * 16 + lr) * BST + wn + nh * 16 + lc * 8);
#pragma unroll
            for (int seg = 0; seg < 2; seg++) {
                uint32_t a[4][4];
#pragma unroll
                for (int mt = 0; mt < 4; mt++)
                    ldsm4(a[mt], sA + (wm + mt * 16 + lr) * AST + seg * 128 + kk * 16 + lc * 8);
#pragma unroll
                for (int mt = 0; mt < 4; mt++)
#pragma unroll
                    for (int nt = 0; nt < 4; nt++) {
                        int nh = nt >> 1, h = (nt & 1) * 2;
                        mma16816(acc[mt][nt], a[mt], b[nh][h], b[nh][h + 1]);
                    }
            }
        }

        bool isSelf = (n0 < out);
#pragma unroll
        for (int mt = 0; mt < 4; mt++) {
#pragma unroll
            for (int nt = 0; nt < 4; nt++) {
                int col = n0 + wn + nt * 8 + tg * 2;
                int r0 = m0 + wm + mt * 16 + g;
                int r1 = r0 + 8;
                if (isSelf) {
                    float b0 = bias[col], b1 = bias[col + 1];
                    if (r0 < NN) {
                        g_Ys[(size_t)r0 * out + col]     = acc[mt][nt][0] + b0;
                        g_Ys[(size_t)r0 * out + col + 1] = acc[mt][nt][1] + b1;
                    }
                    if (r1 < NN) {
                        g_Ys[(size_t)r1 * out + col]     = acc[mt][nt][2] + b0;
                        g_Ys[(size_t)r1 * out + col + 1] = acc[mt][nt][3] + b1;
                    }
                } else {
                    int mc = col - out;
                    if (r0 < NN)
                        *(__half2*)(g_Ym + (size_t)r0 * pitchM + mc) =
                            __floats2half2_rn(acc[mt][nt][0], acc[mt][nt][1]);
                    if (r1 < NN)
                        *(__half2*)(g_Ym + (size_t)r1 * pitchM + mc) =
                            __floats2half2_rn(acc[mt][nt][2], acc[mt][nt][3]);
                }
            }
        }
    }
}

// ---------------- pull aggregation: one warp per node; fused relu+split (+q) epilogue ----------------
// MODE 0: write relu(total) split to g_Asp; MODE 1: write total fp32 to Optr.
// QF: also fill q[batch] into Asp cols [64:128)+[192:256) (layer-0 only).
template <int OUT, int MODE, int QF>
__global__ void __launch_bounds__(256) k_agg(float* __restrict__ Optr,
                                             const int* __restrict__ batch) {
    int w = (blockIdx.x * 256 + threadIdx.x) >> 5;
    if (w >= NN) return;
    int lane = threadIdx.x & 31;
    constexpr int V = OUT / 32;
    constexpr int PITCH = 4 * OUT;
    int start = g_rowptr[w], end = g_rowptr[w + 1];
    float4 iv4 = *(const float4*)(g_inv + w * 4);

    float acc[V];
    {
        const float* sp = g_Ys + (size_t)w * OUT + lane * V;
        if constexpr (V == 4) {
            float4 s = *(const float4*)sp;
            acc[0] = s.x; acc[1] = s.y; acc[2] = s.z; acc[3] = s.w;
        } else {
            float2 s = *(const float2*)sp;
            acc[0] = s.x; acc[1] = s.y;
        }
    }

    int e = start;
    for (; e + 4 <= end; e += 4) {
        int u0 = g_csr[e], u1 = g_csr[e + 1], u2 = g_csr[e + 2], u3 = g_csr[e + 3];
        int s0 = u0 & 0x0FFFFFFF, r0 = ((unsigned)u0) >> 28;
        int s1 = u1 & 0x0FFFFFFF, r1 = ((unsigned)u1) >> 28;
        int s2 = u2 & 0x0FFFFFFF, r2 = ((unsigned)u2) >> 28;
        int s3 = u3 & 0x0FFFFFFF, r3 = ((unsigned)u3) >> 28;
        const __half* p0 = g_Ym + (size_t)s0 * PITCH + r0 * OUT + lane * V;
        const __half* p1 = g_Ym + (size_t)s1 * PITCH + r1 * OUT + lane * V;
        const __half* p2 = g_Ym + (size_t)s2 * PITCH + r2 * OUT + lane * V;
        const __half* p3 = g_Ym + (size_t)s3 * PITCH + r3 * OUT + lane * V;
        float i0 = pick4(iv4, r0), i1 = pick4(iv4, r1);
        float i2 = pick4(iv4, r2), i3 = pick4(iv4, r3);
        if constexpr (V == 4) {
            uint2 w0 = *(const uint2*)p0;
            uint2 w1 = *(const uint2*)p1;
            uint2 w2 = *(const uint2*)p2;
            uint2 w3 = *(const uint2*)p3;
            float2 a0 = __half22float2(*(__half2*)&w0.x), a1 = __half22float2(*(__half2*)&w0.y);
            float2 b0 = __half22float2(*(__half2*)&w1.x), b1 = __half22float2(*(__half2*)&w1.y);
            float2 c0 = __half22float2(*(__half2*)&w2.x), c1 = __half22float2(*(__half2*)&w2.y);
            float2 d0 = __half22float2(*(__half2*)&w3.x), d1 = __half22float2(*(__half2*)&w3.y);
            acc[0] += a0.x * i0; acc[1] += a0.y * i0; acc[2] += a1.x * i0; acc[3] += a1.y * i0;
            acc[0] += b0.x * i1; acc[1] += b0.y * i1; acc[2] += b1.x * i1; acc[3] += b1.y * i1;
            acc[0] += c0.x * i2; acc[1] += c0.y * i2; acc[2] += c1.x * i2; acc[3] += c1.y * i2;
            acc[0] += d0.x * i3; acc[1] += d0.y * i3; acc[2] += d1.x * i3; acc[3] += d1.y * i3;
        } else {
            uint32_t w0 = *(const uint32_t*)p0;
            uint32_t w1 = *(const uint32_t*)p1;
            uint32_t w2 = *(const uint32_t*)p2;
            uint32_t w3 = *(const uint32_t*)p3;
            float2 a0 = __half22float2(*(__half2*)&w0);
            float2 b0 = __half22float2(*(__half2*)&w1);
            float2 c0 = __half22float2(*(__half2*)&w2);
            float2 d0 = __half22float2(*(__half2*)&w3);
            acc[0] += a0.x * i0; acc[1] += a0.y * i0;
            acc[0] += b0.x * i1; acc[1] += b0.y * i1;
            acc[0] += c0.x * i2; acc[1] += c0.y * i2;
            acc[0] += d0.x * i3; acc[1] += d0.y * i3;
        }
    }
    for (; e < end; e++) {
        int u0 = g_csr[e];
        int s0 = u0 & 0x0FFFFFFF, r0 = ((unsigned)u0) >> 28;
        const __half* p0 = g_Ym + (size_t)s0 * PITCH + r0 * OUT + lane * V;
        float i0 = pick4(iv4, r0);
        if constexpr (V == 4) {
            uint2 w0 = *(const uint2*)p0;
            float2 a0 = __half22float2(*(__half2*)&w0.x);
            float2 a1 = __half22float2(*(__half2*)&w0.y);
            acc[0] += a0.x * i0; acc[1] += a0.y * i0;
            acc[2] += a1.x * i0; acc[3] += a1.y * i0;
        } else {
            uint32_t w0 = *(const uint32_t*)p0;
            float2 a0 = __half22float2(*(__half2*)&w0);
            acc[0] += a0.x * i0; acc[1] += a0.y * i0;
        }
    }

    if constexpr (MODE == 0) {
        union { __half h[V]; uint2 u2; uint32_t u1; } ph, pl;
#pragma unroll
        for (int j = 0; j < V; j++) {
            float v = fmaxf(acc[j], 0.0f);
            __half hi = __float2half_rn(v);
            ph.h[j] = hi;
            pl.h[j] = __float2half_rn(v - __half2float(hi));
        }
        __half* base = g_Asp + (size_t)w * 256 + lane * V;
        if constexpr (V == 4) {
            *(uint2*)base         = ph.u2;
            *(uint2*)(base + 128) = pl.u2;
        } else {
            *(uint32_t*)base         = ph.u1;
            *(uint32_t*)(base + 128) = pl.u1;
        }
        if constexpr (QF) {
            int b = batch[w];
            float v0 = g_q[b * 64 + lane * 2], v1 = g_q[b * 64 + lane * 2 + 1];
            __half h0 = __float2half_rn(v0), h1 = __float2half_rn(v1);
            __half l0 = __float2half_rn(v0 - __half2float(h0));
            __half l1 = __float2half_rn(v1 - __half2float(h1));
            __half2 hh; hh.x = h0; hh.y = h1;
            __half2 ll; ll.x = l0; ll.y = l1;
            *(__half2*)(g_Asp + (size_t)w * 256 + 64 + lane * 2)  = hh;
            *(__half2*)(g_Asp + (size_t)w * 256 + 192 + lane * 2) = ll;
        }
    } else {
        float* op = Optr + (size_t)w * OUT + lane * V;
        if constexpr (V == 4) {
            float4 r; r.x = acc[0]; r.y = acc[1]; r.z = acc[2]; r.w = acc[3];
            *(float4*)op = r;
        } else {
            float2 r; r.x = acc[0]; r.y = acc[1];
            *(float2*)op = r;
        }
    }
}

// ---------------- host orchestration ----------------
extern "C" void kernel_launch(void* const* d_in, const int* in_sizes, int n_in,
                              void* d_out, int out_size) {
    const float* x     = (const float*)d_in[0];
    const int*   ei    = (const int*)d_in[1];
    const int*   ea    = (const int*)d_in[2];
    const int*   batch = (const int*)d_in[3];
    const float* qe    = (const float*)d_in[4];
    const float* qnW   = (const float*)d_in[5];
    const float* qnb   = (const float*)d_in[6];
    const float* W0 = (const float*)d_in[7],  *root0 = (const float*)d_in[8],  *b0 = (const float*)d_in[9];
    const float* W1 = (const float*)d_in[10], *root1 = (const float*)d_in[11], *b1 = (const float*)d_in[12];
    const float* W2 = (const float*)d_in[13], *root2 = (const float*)d_in[14], *b2 = (const float*)d_in[15];
    const float* W3 = (const float*)d_in[16], *root3 = (const float*)d_in[17], *b3 = (const float*)d_in[18];
    float* out = (float*)d_out;

    const int* src = ei;
    const int* dst = ei + EE;

    cudaFuncSetAttribute(k_gemm, cudaFuncAttributeMaxDynamicSharedMemorySize, GEMM_SMEM);

    const int MG = 391;                       // ceil(50000/128)
    const int AGG_G = (NN * 32 + 255) / 256;  // 6250

    // k_gemm is launch #4 so ncu -s captures it.
    k_prepA0<<<(NN * 128 + 255) / 256, 256>>>(x);              // 1 (also zeroes g_cnt)
    k_prepB<<<(128 * 320 + 255) / 256, 256>>>(root0, W0, 64);  // 2
    k_q<<<GG, 64>>>(qe, qnW, qnb);                             // 3
    k_gemm<<<MG, 128, GEMM_SMEM>>>(b0, 64, 5);                 // 4 (profiled)
    k_count<<<(EE + 255) / 256, 256>>>(dst, ea);               // 5
    k_scan1<<<196, 256>>>();                                   // 6
    k_scan2<<<1, 256>>>();                                     // 7
    k_scan3<<<196, 256>>>();                                   // 8
    k_fill<<<(EE + 255) / 256, 256>>>(src, dst, ea);           // 9

    // Layer 0 aggregation (+ fused q[batch] fill)
    k_agg<64, 0, 1><<<AGG_G, 256>>>(nullptr, batch);

    // Layer 1: in=128, out=128
    k_prepB<<<(128 * 640 + 255) / 256, 256>>>(root1, W1, 128);
    k_gemm<<<MG, 128, GEMM_SMEM>>>(b1, 128, 10);
    k_agg<128, 0, 0><<<AGG_G, 256>>>(nullptr, nullptr);

    // Layer 2: in=128, out=128
    k_prepB<<<(128 * 640 + 255) / 256, 256>>>(root2, W2, 128);
    k_gemm<<<MG, 128, GEMM_SMEM>>>(b2, 128, 10);
    k_agg<128, 0, 0><<<AGG_G, 256>>>(nullptr, nullptr);

    // Layer 3: in=128, out=64 -> d_out
    k_prepB<<<(128 * 320 + 255) / 256, 256>>>(root3, W3, 64);
    k_gemm<<<MG, 128, GEMM_SMEM>>>(b3, 64, 5);
    k_agg<64, 1, 0><<<AGG_G, 256>>>(out, nullptr);
}

// round 6
// speedup vs baseline: 2.5216x; 1.0030x over previous
#include <cuda_runtime.h>
#include <cuda_bf16.h>
#include <cuda_fp16.h>
#include <cstdint>

#define NN 50000
#define EE 800000
#define RR 4
#define GG 16

// ---------------- scratch (device globals; no allocation) ----------------
__device__ float   g_Ys[NN * 128];          // self+bias, fp32 [N][out]
__device__ __half  g_Ym[NN * 512];          // messages fp16 [N][4*out] (L2-resident)
__device__ __half  g_Asp[NN * 256];         // split activations [N][Ah(128)|Al(128)] fp16
__device__ __half  g_Bsp[128 * 640];        // weights fp16, row-major [k][5*out]
__device__ float   g_q[GG * 64];
__device__ int     g_cnt[RR * NN];
__device__ float   g_inv[NN * 4];
__device__ int     g_deg[NN];
__device__ int     g_part[256];
__device__ int     g_rowptr[NN + 1];
__device__ int     g_fill[NN];
__device__ int     g_csr[EE];               // src | (rel<<28)

// ---------------- helpers ----------------
__device__ __forceinline__ uint32_t smem_u32(const void* p) {
    return (uint32_t)__cvta_generic_to_shared(p);
}
__device__ __forceinline__ void ldsm4(uint32_t* d, const __half* p) {
    uint32_t a = smem_u32(p);
    asm volatile("ldmatrix.sync.aligned.m8n8.x4.shared.b16 {%0,%1,%2,%3}, [%4];"
                 : "=r"(d[0]), "=r"(d[1]), "=r"(d[2]), "=r"(d[3]) : "r"(a));
}
__device__ __forceinline__ void ldsm4t(uint32_t* d, const __half* p) {
    uint32_t a = smem_u32(p);
    asm volatile("ldmatrix.sync.aligned.m8n8.x4.trans.shared.b16 {%0,%1,%2,%3}, [%4];"
                 : "=r"(d[0]), "=r"(d[1]), "=r"(d[2]), "=r"(d[3]) : "r"(a));
}
__device__ __forceinline__ void mma16816(float* c, const uint32_t* a, uint32_t b0, uint32_t b1) {
    asm volatile(
        "mma.sync.aligned.m16n8k16.row.col.f32.f16.f16.f32 "
        "{%0,%1,%2,%3}, {%4,%5,%6,%7}, {%8,%9}, {%0,%1,%2,%3};"
        : "+f"(c[0]), "+f"(c[1]), "+f"(c[2]), "+f"(c[3])
        : "r"(a[0]), "r"(a[1]), "r"(a[2]), "r"(a[3]), "r"(b0), "r"(b1));
}
__device__ __forceinline__ void cp_async16(uint32_t smem_addr, const void* gptr) {
    asm volatile("cp.async.cg.shared.global [%0], [%1], 16;" :: "r"(smem_addr), "l"(gptr));
}
__device__ __forceinline__ void cp_commit() {
    asm volatile("cp.async.commit_group;" ::: "memory");
}
__device__ __forceinline__ void cp_wait0() {
    asm volatile("cp.async.wait_group 0;" ::: "memory");
}
__device__ __forceinline__ float pick4(float4 v, int r) {
    return r == 0 ? v.x : (r == 1 ? v.y : (r == 2 ? v.z : v.w));
}

// ---------------- layer-0 activation split from x (+ zero g_cnt) ----------------
__global__ void k_prepA0(const float* __restrict__ x) {
    int idx = blockIdx.x * blockDim.x + threadIdx.x;
    if (idx < RR * NN) g_cnt[idx] = 0;
    if (idx >= NN * 128) return;
    int i = idx >> 7, k = idx & 127;
    float v = x[idx];
    __half hi = __float2half_rn(v);
    float lo = v - __half2float(hi);
    g_Asp[i * 256 + k]       = hi;
    g_Asp[i * 256 + 128 + k] = __float2half_rn(lo);
}

// ---------------- weight concat fp16: B[k][5*out] ----------------
__global__ void k_prepB(const float* __restrict__ root, const float* __restrict__ W, int out) {
    int ncols = 5 * out;
    int idx = blockIdx.x * blockDim.x + threadIdx.x;
    if (idx >= 128 * ncols) return;
    int k = idx / ncols, j = idx % ncols;
    float v = (j < out) ? root[k * out + j]
                        : W[((j / out - 1) * 128 + k) * out + (j % out)];
    g_Bsp[idx] = __float2half_rn(v);
}

// ---------------- question projection ----------------
__global__ void k_q(const float* __restrict__ qe, const float* __restrict__ qnW,
                    const float* __restrict__ qnb) {
    __shared__ float sq[768];
    int g = blockIdx.x, j = threadIdx.x;
    for (int i = j; i < 768; i += 64) sq[i] = qe[g * 768 + i];
    __syncthreads();
    float acc = qnb[j];
    for (int k = 0; k < 768; k++) acc = fmaf(sq[k], qnW[k * 64 + j], acc);
    g_q[g * 64 + j] = fmaxf(acc, 0.0f);
}

// ---------------- CSR build ----------------
__global__ void k_count(const int* __restrict__ dst, const int* __restrict__ ea) {
    int e = blockIdx.x * blockDim.x + threadIdx.x;
    if (e >= EE) return;
    atomicAdd(&g_cnt[ea[e] * NN + dst[e]], 1);
}
__global__ void k_scan1() {
    int t = threadIdx.x;
    int i = blockIdx.x * 256 + t;
    int tot = 0;
    if (i < NN) {
#pragma unroll
        for (int r = 0; r < RR; r++) {
            int c = g_cnt[r * NN + i];
            tot += c;
            g_inv[i * 4 + r] = 1.0f / (float)max(c, 1);
        }
        g_deg[i] = tot;
    }
    __shared__ int s[256];
    s[t] = tot;
    __syncthreads();
    for (int d = 128; d; d >>= 1) {
        if (t < d) s[t] += s[t + d];
        __syncthreads();
    }
    if (t == 0) g_part[blockIdx.x] = s[0];
}
__global__ void k_scan2() {
    __shared__ int s[256];
    int t = threadIdx.x;
    int v = (t < 196) ? g_part[t] : 0;
    s[t] = v;
    __syncthreads();
    for (int d = 1; d < 256; d <<= 1) {
        int x = (t >= d) ? s[t - d] : 0;
        __syncthreads();
        s[t] += x;
        __syncthreads();
    }
    if (t < 196) g_part[t] = s[t] - v;
    if (t == 255) g_rowptr[NN] = s[255];
}
__global__ void k_scan3() {
    int t = threadIdx.x;
    int i = blockIdx.x * 256 + t;
    int v = (i < NN) ? g_deg[i] : 0;
    __shared__ int s[256];
    s[t] = v;
    __syncthreads();
    for (int d = 1; d < 256; d <<= 1) {
        int x = (t >= d) ? s[t - d] : 0;
        __syncthreads();
        s[t] += x;
        __syncthreads();
    }
    if (i < NN) {
        int off = g_part[blockIdx.x] + s[t] - v;
        g_rowptr[i] = off;
        g_fill[i] = off;
    }
}
__global__ void k_fill(const int* __restrict__ src, const int* __restrict__ dst,
                       const int* __restrict__ ea) {
    int e = blockIdx.x * blockDim.x + threadIdx.x;
    if (e >= EE) return;
    int d = dst[e];
    int pos = atomicAdd(&g_fill[d], 1);
    g_csr[pos] = src[e] | (ea[e] << 28);
}

// ---------------- GEMM: 64-row CTAs, 128 thr, warp 32x64, 128-col iterations ----------------
#define AST 264   // 256 + 8 pad (halves)
#define BST 136   // 128 + 8 pad (halves)
#define GEMM_SMEM ((64 * AST + 128 * BST) * 2)   // 33.8K + 34.8K = 68.6KB -> 3 CTA/SM

__global__ void __launch_bounds__(128) k_gemm(const float* __restrict__ bias,
                                              int out, int niter) {
    extern __shared__ __half smem[];
    __half* sA = smem;                 // [64][AST]
    __half* sB = smem + 64 * AST;      // [128][BST]
    int m0 = blockIdx.x * 64;
    int t = threadIdx.x;
    int ncols = 5 * out;

    // load A tile (64 x 256 halves = 2048 uint4, 16 per thread)
#pragma unroll
    for (int i = 0; i < 16; i++) {
        int idx = t + i * 128;
        int row = idx >> 5;
        int c8 = (idx & 31) * 8;
        int grow = m0 + row;
        uint4 val = make_uint4(0, 0, 0, 0);
        if (grow < NN) val = *(const uint4*)(g_Asp + (size_t)grow * 256 + c8);
        *(uint4*)(sA + row * AST + c8) = val;
    }

    int w = t >> 5, lane = t & 31;
    int wm = (w & 1) * 32, wn = (w >> 1) * 64;
    int lr = lane & 15, lc = lane >> 4;
    int g = lane >> 2, tg = lane & 3;
    int pitchM = 4 * out;

    for (int nb = 0; nb < niter; nb++) {
        int n0 = nb * 128;
        __syncthreads();   // prior compute done before overwriting B; A visible on first pass
        // load B tile (128 rows x 128 cols = 2048 uint4, 16 per thread) via cp.async
        {
            uint32_t sbb = smem_u32(sB);
#pragma unroll
            for (int i = 0; i < 16; i++) {
                int idx = t + i * 128;
                int row = idx >> 4;
                int c8 = (idx & 15) * 8;
                cp_async16(sbb + (row * BST + c8) * 2, g_Bsp + (size_t)row * ncols + n0 + c8);
            }
            cp_commit();
            cp_wait0();
        }
        __syncthreads();

        float acc[2][8][4];
#pragma unroll
        for (int mt = 0; mt < 2; mt++)
#pragma unroll
            for (int nt = 0; nt < 8; nt++)
#pragma unroll
                for (int i = 0; i < 4; i++) acc[mt][nt][i] = 0.0f;

#pragma unroll
        for (int kk = 0; kk < 8; kk++) {
            uint32_t b[4][4];
#pragma unroll
            for (int nh = 0; nh < 4; nh++)
                ldsm4t(b[nh], sB + (kk * 16 + lr) * BST + wn + nh * 16 + lc * 8);
#pragma unroll
            for (int seg = 0; seg < 2; seg++) {
                uint32_t a[2][4];
#pragma unroll
                for (int mt = 0; mt < 2; mt++)
                    ldsm4(a[mt], sA + (wm + mt * 16 + lr) * AST + seg * 128 + kk * 16 + lc * 8);
#pragma unroll
                for (int mt = 0; mt < 2; mt++)
#pragma unroll
                    for (int nt = 0; nt < 8; nt++) {
                        int nh = nt >> 1, h = (nt & 1) * 2;
                        mma16816(acc[mt][nt], a[mt], b[nh][h], b[nh][h + 1]);
                    }
            }
        }

#pragma unroll
        for (int mt = 0; mt < 2; mt++) {
#pragma unroll
            for (int nt = 0; nt < 8; nt++) {
                int col = n0 + wn + nt * 8 + tg * 2;
                if (col >= ncols) continue;
                int r0 = m0 + wm + mt * 16 + g;
                int r1 = r0 + 8;
                if (col < out) {
                    float b0 = bias[col], b1 = bias[col + 1];
                    if (r0 < NN) {
                        g_Ys[(size_t)r0 * out + col]     = acc[mt][nt][0] + b0;
                        g_Ys[(size_t)r0 * out + col + 1] = acc[mt][nt][1] + b1;
                    }
                    if (r1 < NN) {
                        g_Ys[(size_t)r1 * out + col]     = acc[mt][nt][2] + b0;
                        g_Ys[(size_t)r1 * out + col + 1] = acc[mt][nt][3] + b1;
                    }
                } else {
                    int mc = col - out;
                    if (r0 < NN)
                        *(__half2*)(g_Ym + (size_t)r0 * pitchM + mc) =
                            __floats2half2_rn(acc[mt][nt][0], acc[mt][nt][1]);
                    if (r1 < NN)
                        *(__half2*)(g_Ym + (size_t)r1 * pitchM + mc) =
                            __floats2half2_rn(acc[mt][nt][2], acc[mt][nt][3]);
                }
            }
        }
    }
}

// ---------------- pull aggregation: one warp per node; fused relu+split (+q) epilogue ----------------
template <int OUT, int MODE, int QF>
__global__ void __launch_bounds__(256) k_agg(float* __restrict__ Optr,
                                             const int* __restrict__ batch) {
    int w = (blockIdx.x * 256 + threadIdx.x) >> 5;
    if (w >= NN) return;
    int lane = threadIdx.x & 31;
    constexpr int V = OUT / 32;
    constexpr int PITCH = 4 * OUT;
    int start = g_rowptr[w], end = g_rowptr[w + 1];
    float4 iv4 = *(const float4*)(g_inv + w * 4);

    float acc[V];
    {
        const float* sp = g_Ys + (size_t)w * OUT + lane * V;
        if constexpr (V == 4) {
            float4 s = *(const float4*)sp;
            acc[0] = s.x; acc[1] = s.y; acc[2] = s.z; acc[3] = s.w;
        } else {
            float2 s = *(const float2*)sp;
            acc[0] = s.x; acc[1] = s.y;
        }
    }

    int e = start;
    for (; e + 4 <= end; e += 4) {
        int u0 = g_csr[e], u1 = g_csr[e + 1], u2 = g_csr[e + 2], u3 = g_csr[e + 3];
        int s0 = u0 & 0x0FFFFFFF, r0 = ((unsigned)u0) >> 28;
        int s1 = u1 & 0x0FFFFFFF, r1 = ((unsigned)u1) >> 28;
        int s2 = u2 & 0x0FFFFFFF, r2 = ((unsigned)u2) >> 28;
        int s3 = u3 & 0x0FFFFFFF, r3 = ((unsigned)u3) >> 28;
        const __half* p0 = g_Ym + (size_t)s0 * PITCH + r0 * OUT + lane * V;
        const __half* p1 = g_Ym + (size_t)s1 * PITCH + r1 * OUT + lane * V;
        const __half* p2 = g_Ym + (size_t)s2 * PITCH + r2 * OUT + lane * V;
        const __half* p3 = g_Ym + (size_t)s3 * PITCH + r3 * OUT + lane * V;
        float i0 = pick4(iv4, r0), i1 = pick4(iv4, r1);
        float i2 = pick4(iv4, r2), i3 = pick4(iv4, r3);
        if constexpr (V == 4) {
            uint2 w0 = *(const uint2*)p0;
            uint2 w1 = *(const uint2*)p1;
            uint2 w2 = *(const uint2*)p2;
            uint2 w3 = *(const uint2*)p3;
            float2 a0 = __half22float2(*(__half2*)&w0.x), a1 = __half22float2(*(__half2*)&w0.y);
            float2 b0 = __half22float2(*(__half2*)&w1.x), b1 = __half22float2(*(__half2*)&w1.y);
            float2 c0 = __half22float2(*(__half2*)&w2.x), c1 = __half22float2(*(__half2*)&w2.y);
            float2 d0 = __half22float2(*(__half2*)&w3.x), d1 = __half22float2(*(__half2*)&w3.y);
            acc[0] += a0.x * i0; acc[1] += a0.y * i0; acc[2] += a1.x * i0; acc[3] += a1.y * i0;
            acc[0] += b0.x * i1; acc[1] += b0.y * i1; acc[2] += b1.x * i1; acc[3] += b1.y * i1;
            acc[0] += c0.x * i2; acc[1] += c0.y * i2; acc[2] += c1.x * i2; acc[3] += c1.y * i2;
            acc[0] += d0.x * i3; acc[1] += d0.y * i3; acc[2] += d1.x * i3; acc[3] += d1.y * i3;
        } else {
            uint32_t w0 = *(const uint32_t*)p0;
            uint32_t w1 = *(const uint32_t*)p1;
            uint32_t w2 = *(const uint32_t*)p2;
            uint32_t w3 = *(const uint32_t*)p3;
            float2 a0 = __half22float2(*(__half2*)&w0);
            float2 b0 = __half22float2(*(__half2*)&w1);
            float2 c0 = __half22float2(*(__half2*)&w2);
            float2 d0 = __half22float2(*(__half2*)&w3);
            acc[0] += a0.x * i0; acc[1] += a0.y * i0;
            acc[0] += b0.x * i1; acc[1] += b0.y * i1;
            acc[0] += c0.x * i2; acc[1] += c0.y * i2;
            acc[0] += d0.x * i3; acc[1] += d0.y * i3;
        }
    }
    for (; e < end; e++) {
        int u0 = g_csr[e];
        int s0 = u0 & 0x0FFFFFFF, r0 = ((unsigned)u0) >> 28;
        const __half* p0 = g_Ym + (size_t)s0 * PITCH + r0 * OUT + lane * V;
        float i0 = pick4(iv4, r0);
        if constexpr (V == 4) {
            uint2 w0 = *(const uint2*)p0;
            float2 a0 = __half22float2(*(__half2*)&w0.x);
            float2 a1 = __half22float2(*(__half2*)&w0.y);
            acc[0] += a0.x * i0; acc[1] += a0.y * i0;
            acc[2] += a1.x * i0; acc[3] += a1.y * i0;
        } else {
            uint32_t w0 = *(const uint32_t*)p0;
            float2 a0 = __half22float2(*(__half2*)&w0);
            acc[0] += a0.x * i0; acc[1] += a0.y * i0;
        }
    }

    if constexpr (MODE == 0) {
        union { __half h[V]; uint2 u2; uint32_t u1; } ph, pl;
#pragma unroll
        for (int j = 0; j < V; j++) {
            float v = fmaxf(acc[j], 0.0f);
            __half hi = __float2half_rn(v);
            ph.h[j] = hi;
            pl.h[j] = __float2half_rn(v - __half2float(hi));
        }
        __half* base = g_Asp + (size_t)w * 256 + lane * V;
        if constexpr (V == 4) {
            *(uint2*)base         = ph.u2;
            *(uint2*)(base + 128) = pl.u2;
        } else {
            *(uint32_t*)base         = ph.u1;
            *(uint32_t*)(base + 128) = pl.u1;
        }
        if constexpr (QF) {
            int b = batch[w];
            float v0 = g_q[b * 64 + lane * 2], v1 = g_q[b * 64 + lane * 2 + 1];
            __half h0 = __float2half_rn(v0), h1 = __float2half_rn(v1);
            __half l0 = __float2half_rn(v0 - __half2float(h0));
            __half l1 = __float2half_rn(v1 - __half2float(h1));
            __half2 hh; hh.x = h0; hh.y = h1;
            __half2 ll; ll.x = l0; ll.y = l1;
            *(__half2*)(g_Asp + (size_t)w * 256 + 64 + lane * 2)  = hh;
            *(__half2*)(g_Asp + (size_t)w * 256 + 192 + lane * 2) = ll;
        }
    } else {
        float* op = Optr + (size_t)w * OUT + lane * V;
        if constexpr (V == 4) {
            float4 r; r.x = acc[0]; r.y = acc[1]; r.z = acc[2]; r.w = acc[3];
            *(float4*)op = r;
        } else {
            float2 r; r.x = acc[0]; r.y = acc[1];
            *(float2*)op = r;
        }
    }
}

// ---------------- host orchestration ----------------
extern "C" void kernel_launch(void* const* d_in, const int* in_sizes, int n_in,
                              void* d_out, int out_size) {
    const float* x     = (const float*)d_in[0];
    const int*   ei    = (const int*)d_in[1];
    const int*   ea    = (const int*)d_in[2];
    const int*   batch = (const int*)d_in[3];
    const float* qe    = (const float*)d_in[4];
    const float* qnW   = (const float*)d_in[5];
    const float* qnb   = (const float*)d_in[6];
    const float* W0 = (const float*)d_in[7],  *root0 = (const float*)d_in[8],  *b0 = (const float*)d_in[9];
    const float* W1 = (const float*)d_in[10], *root1 = (const float*)d_in[11], *b1 = (const float*)d_in[12];
    const float* W2 = (const float*)d_in[13], *root2 = (const float*)d_in[14], *b2 = (const float*)d_in[15];
    const float* W3 = (const float*)d_in[16], *root3 = (const float*)d_in[17], *b3 = (const float*)d_in[18];
    float* out = (float*)d_out;

    const int* src = ei;
    const int* dst = ei + EE;

    cudaFuncSetAttribute(k_gemm, cudaFuncAttributeMaxDynamicSharedMemorySize, GEMM_SMEM);

    const int MG = 782;                       // ceil(50000/64)
    const int AGG_G = (NN * 32 + 255) / 256;  // 6250

    // k_gemm is launch #4 so ncu -s captures it.
    k_prepA0<<<(NN * 128 + 255) / 256, 256>>>(x);              // 1 (also zeroes g_cnt)
    k_prepB<<<(128 * 320 + 255) / 256, 256>>>(root0, W0, 64);  // 2
    k_q<<<GG, 64>>>(qe, qnW, qnb);                             // 3
    k_gemm<<<MG, 128, GEMM_SMEM>>>(b0, 64, 3);                 // 4 (profiled)
    k_count<<<(EE + 255) / 256, 256>>>(dst, ea);               // 5
    k_scan1<<<196, 256>>>();                                   // 6
    k_scan2<<<1, 256>>>();                                     // 7
    k_scan3<<<196, 256>>>();                                   // 8
    k_fill<<<(EE + 255) / 256, 256>>>(src, dst, ea);           // 9

    // Layer 0 aggregation (+ fused q[batch] fill)
    k_agg<64, 0, 1><<<AGG_G, 256>>>(nullptr, batch);

    // Layer 1: in=128, out=128
    k_prepB<<<(128 * 640 + 255) / 256, 256>>>(root1, W1, 128);
    k_gemm<<<MG, 128, GEMM_SMEM>>>(b1, 128, 5);
    k_agg<128, 0, 0><<<AGG_G, 256>>>(nullptr, nullptr);

    // Layer 2: in=128, out=128
    k_prepB<<<(128 * 640 + 255) / 256, 256>>>(root2, W2, 128);
    k_gemm<<<MG, 128, GEMM_SMEM>>>(b2, 128, 5);
    k_agg<128, 0, 0><<<AGG_G, 256>>>(nullptr, nullptr);

    // Layer 3: in=128, out=64 -> d_out
    k_prepB<<<(128 * 320 + 255) / 256, 256>>>(root3, W3, 64);
    k_gemm<<<MG, 128, GEMM_SMEM>>>(b3, 64, 3);
    k_agg<64, 1, 0><<<AGG_G, 256>>>(out, nullptr);
}

// round 7
// speedup vs baseline: 2.8593x; 1.1339x over previous
#include <cuda_runtime.h>
#include <cuda_bf16.h>
#include <cuda_fp16.h>
#include <cstdint>

#define NN 50000
#define EE 800000
#define RR 4
#define GG 16

// ---------------- scratch (device globals; no allocation) ----------------
__device__ float   g_Ys[NN * 128];          // self+bias, fp32 [N][out]
__device__ __half  g_Ym[NN * 512];          // messages fp16 [N][4*out] (L2-resident)
__device__ __half  g_Asp[NN * 128];         // activations fp16 [N][128]
__device__ __half  g_Bsp[128 * 640];        // weights fp16, row-major [k][5*out]
__device__ float   g_q[GG * 64];
__device__ int     g_cnt[RR * NN];
__device__ float   g_inv[NN * 4];
__device__ int     g_deg[NN];
__device__ int     g_part[256];
__device__ int     g_rowptr[NN + 1];
__device__ int     g_fill[NN];
__device__ int     g_csr[EE];               // src | (rel<<28)

// ---------------- helpers ----------------
__device__ __forceinline__ uint32_t smem_u32(const void* p) {
    return (uint32_t)__cvta_generic_to_shared(p);
}
__device__ __forceinline__ void ldsm4(uint32_t* d, const __half* p) {
    uint32_t a = smem_u32(p);
    asm volatile("ldmatrix.sync.aligned.m8n8.x4.shared.b16 {%0,%1,%2,%3}, [%4];"
                 : "=r"(d[0]), "=r"(d[1]), "=r"(d[2]), "=r"(d[3]) : "r"(a));
}
__device__ __forceinline__ void ldsm4t(uint32_t* d, const __half* p) {
    uint32_t a = smem_u32(p);
    asm volatile("ldmatrix.sync.aligned.m8n8.x4.trans.shared.b16 {%0,%1,%2,%3}, [%4];"
                 : "=r"(d[0]), "=r"(d[1]), "=r"(d[2]), "=r"(d[3]) : "r"(a));
}
__device__ __forceinline__ void mma16816(float* c, const uint32_t* a, uint32_t b0, uint32_t b1) {
    asm volatile(
        "mma.sync.aligned.m16n8k16.row.col.f32.f16.f16.f32 "
        "{%0,%1,%2,%3}, {%4,%5,%6,%7}, {%8,%9}, {%0,%1,%2,%3};"
        : "+f"(c[0]), "+f"(c[1]), "+f"(c[2]), "+f"(c[3])
        : "r"(a[0]), "r"(a[1]), "r"(a[2]), "r"(a[3]), "r"(b0), "r"(b1));
}
__device__ __forceinline__ void cp_async16(uint32_t smem_addr, const void* gptr) {
    asm volatile("cp.async.cg.shared.global [%0], [%1], 16;" :: "r"(smem_addr), "l"(gptr));
}
__device__ __forceinline__ void cp_commit() {
    asm volatile("cp.async.commit_group;" ::: "memory");
}
__device__ __forceinline__ void cp_wait0() {
    asm volatile("cp.async.wait_group 0;" ::: "memory");
}
__device__ __forceinline__ float pick4(float4 v, int r) {
    return r == 0 ? v.x : (r == 1 ? v.y : (r == 2 ? v.z : v.w));
}

// ---------------- layer-0 activation fp16 from x (+ zero g_cnt) ----------------
__global__ void k_prepA0(const float* __restrict__ x) {
    int idx = blockIdx.x * blockDim.x + threadIdx.x;
    if (idx < RR * NN) g_cnt[idx] = 0;
    if (idx >= NN * 128) return;
    g_Asp[idx] = __float2half_rn(x[idx]);
}

// ---------------- weight concat fp16: B[k][5*out] ----------------
__global__ void k_prepB(const float* __restrict__ root, const float* __restrict__ W, int out) {
    int ncols = 5 * out;
    int idx = blockIdx.x * blockDim.x + threadIdx.x;
    if (idx >= 128 * ncols) return;
    int k = idx / ncols, j = idx % ncols;
    float v = (j < out) ? root[k * out + j]
                        : W[((j / out - 1) * 128 + k) * out + (j % out)];
    g_Bsp[idx] = __float2half_rn(v);
}

// ---------------- question projection ----------------
__global__ void k_q(const float* __restrict__ qe, const float* __restrict__ qnW,
                    const float* __restrict__ qnb) {
    __shared__ float sq[768];
    int g = blockIdx.x, j = threadIdx.x;
    for (int i = j; i < 768; i += 64) sq[i] = qe[g * 768 + i];
    __syncthreads();
    float acc = qnb[j];
    for (int k = 0; k < 768; k++) acc = fmaf(sq[k], qnW[k * 64 + j], acc);
    g_q[g * 64 + j] = fmaxf(acc, 0.0f);
}

// ---------------- CSR build ----------------
__global__ void k_count(const int* __restrict__ dst, const int* __restrict__ ea) {
    int e = blockIdx.x * blockDim.x + threadIdx.x;
    if (e >= EE) return;
    atomicAdd(&g_cnt[ea[e] * NN + dst[e]], 1);
}
__global__ void k_scan1() {
    int t = threadIdx.x;
    int i = blockIdx.x * 256 + t;
    int tot = 0;
    if (i < NN) {
#pragma unroll
        for (int r = 0; r < RR; r++) {
            int c = g_cnt[r * NN + i];
            tot += c;
            g_inv[i * 4 + r] = 1.0f / (float)max(c, 1);
        }
        g_deg[i] = tot;
    }
    __shared__ int s[256];
    s[t] = tot;
    __syncthreads();
    for (int d = 128; d; d >>= 1) {
        if (t < d) s[t] += s[t + d];
        __syncthreads();
    }
    if (t == 0) g_part[blockIdx.x] = s[0];
}
__global__ void k_scan2() {
    __shared__ int s[256];
    int t = threadIdx.x;
    int v = (t < 196) ? g_part[t] : 0;
    s[t] = v;
    __syncthreads();
    for (int d = 1; d < 256; d <<= 1) {
        int x = (t >= d) ? s[t - d] : 0;
        __syncthreads();
        s[t] += x;
        __syncthreads();
    }
    if (t < 196) g_part[t] = s[t] - v;
    if (t == 255) g_rowptr[NN] = s[255];
}
__global__ void k_scan3() {
    int t = threadIdx.x;
    int i = blockIdx.x * 256 + t;
    int v = (i < NN) ? g_deg[i] : 0;
    __shared__ int s[256];
    s[t] = v;
    __syncthreads();
    for (int d = 1; d < 256; d <<= 1) {
        int x = (t >= d) ? s[t - d] : 0;
        __syncthreads();
        s[t] += x;
        __syncthreads();
    }
    if (i < NN) {
        int off = g_part[blockIdx.x] + s[t] - v;
        g_rowptr[i] = off;
        g_fill[i] = off;
    }
}
__global__ void k_fill(const int* __restrict__ src, const int* __restrict__ dst,
                       const int* __restrict__ ea) {
    int e = blockIdx.x * blockDim.x + threadIdx.x;
    if (e >= EE) return;
    int d = dst[e];
    int pos = atomicAdd(&g_fill[d], 1);
    g_csr[pos] = src[e] | (ea[e] << 28);
}

// ---------------- GEMM: 64-row CTAs, 128 thr, warp 32x64, K=128 single-term ----------------
#define AST 136   // 128 + 8 pad (halves)
#define BST 136
#define GEMM_SMEM ((64 * AST + 128 * BST) * 2)   // 17.4K + 34.8K = 52.2KB -> 4 CTA/SM

__global__ void __launch_bounds__(128, 4) k_gemm(const float* __restrict__ bias,
                                                 int out, int niter) {
    extern __shared__ __half smem[];
    __half* sA = smem;                 // [64][AST]
    __half* sB = smem + 64 * AST;      // [128][BST]
    int m0 = blockIdx.x * 64;
    int t = threadIdx.x;
    int ncols = 5 * out;

    // load A tile (64 x 128 halves = 1024 uint4, 8 per thread)
#pragma unroll
    for (int i = 0; i < 8; i++) {
        int idx = t + i * 128;
        int row = idx >> 4;
        int c8 = (idx & 15) * 8;
        int grow = m0 + row;
        uint4 val = make_uint4(0, 0, 0, 0);
        if (grow < NN) val = *(const uint4*)(g_Asp + (size_t)grow * 128 + c8);
        *(uint4*)(sA + row * AST + c8) = val;
    }

    int w = t >> 5, lane = t & 31;
    int wm = (w & 1) * 32, wn = (w >> 1) * 64;
    int lr = lane & 15, lc = lane >> 4;
    int g = lane >> 2, tg = lane & 3;
    int pitchM = 4 * out;

    for (int nb = 0; nb < niter; nb++) {
        int n0 = nb * 128;
        __syncthreads();   // prior compute done before overwriting B; A visible on first pass
        // load B tile (128 rows x 128 cols = 2048 uint4, 16 per thread) via cp.async
        {
            uint32_t sbb = smem_u32(sB);
#pragma unroll
            for (int i = 0; i < 16; i++) {
                int idx = t + i * 128;
                int row = idx >> 4;
                int c8 = (idx & 15) * 8;
                cp_async16(sbb + (row * BST + c8) * 2, g_Bsp + (size_t)row * ncols + n0 + c8);
            }
            cp_commit();
            cp_wait0();
        }
        __syncthreads();

        float acc[2][8][4];
#pragma unroll
        for (int mt = 0; mt < 2; mt++)
#pragma unroll
            for (int nt = 0; nt < 8; nt++)
#pragma unroll
                for (int i = 0; i < 4; i++) acc[mt][nt][i] = 0.0f;

#pragma unroll
        for (int kk = 0; kk < 8; kk++) {
            uint32_t b[4][4];
#pragma unroll
            for (int nh = 0; nh < 4; nh++)
                ldsm4t(b[nh], sB + (kk * 16 + lr) * BST + wn + nh * 16 + lc * 8);
            uint32_t a[2][4];
#pragma unroll
            for (int mt = 0; mt < 2; mt++)
                ldsm4(a[mt], sA + (wm + mt * 16 + lr) * AST + kk * 16 + lc * 8);
#pragma unroll
            for (int mt = 0; mt < 2; mt++)
#pragma unroll
                for (int nt = 0; nt < 8; nt++) {
                    int nh = nt >> 1, h = (nt & 1) * 2;
                    mma16816(acc[mt][nt], a[mt], b[nh][h], b[nh][h + 1]);
                }
        }

#pragma unroll
        for (int mt = 0; mt < 2; mt++) {
#pragma unroll
            for (int nt = 0; nt < 8; nt++) {
                int col = n0 + wn + nt * 8 + tg * 2;
                if (col >= ncols) continue;
                int r0 = m0 + wm + mt * 16 + g;
                int r1 = r0 + 8;
                if (col < out) {
                    float b0 = bias[col], b1 = bias[col + 1];
                    if (r0 < NN) {
                        g_Ys[(size_t)r0 * out + col]     = acc[mt][nt][0] + b0;
                        g_Ys[(size_t)r0 * out + col + 1] = acc[mt][nt][1] + b1;
                    }
                    if (r1 < NN) {
                        g_Ys[(size_t)r1 * out + col]     = acc[mt][nt][2] + b0;
                        g_Ys[(size_t)r1 * out + col + 1] = acc[mt][nt][3] + b1;
                    }
                } else {
                    int mc = col - out;
                    if (r0 < NN)
                        *(__half2*)(g_Ym + (size_t)r0 * pitchM + mc) =
                            __floats2half2_rn(acc[mt][nt][0], acc[mt][nt][1]);
                    if (r1 < NN)
                        *(__half2*)(g_Ym + (size_t)r1 * pitchM + mc) =
                            __floats2half2_rn(acc[mt][nt][2], acc[mt][nt][3]);
                }
            }
        }
    }
}

// ---------------- pull aggregation: one warp per node; fused relu (+q) epilogue ----------------
// MODE 0: write relu(total) fp16 to g_Asp[N][128]; MODE 1: write total fp32 to Optr.
// QF: also fill q[batch] fp16 into Asp cols [64:128) (layer-0 only).
template <int OUT, int MODE, int QF>
__global__ void __launch_bounds__(256) k_agg(float* __restrict__ Optr,
                                             const int* __restrict__ batch) {
    int w = (blockIdx.x * 256 + threadIdx.x) >> 5;
    if (w >= NN) return;
    int lane = threadIdx.x & 31;
    constexpr int V = OUT / 32;
    constexpr int PITCH = 4 * OUT;
    int start = g_rowptr[w], end = g_rowptr[w + 1];
    float4 iv4 = *(const float4*)(g_inv + w * 4);

    float acc[V];
    {
        const float* sp = g_Ys + (size_t)w * OUT + lane * V;
        if constexpr (V == 4) {
            float4 s = *(const float4*)sp;
            acc[0] = s.x; acc[1] = s.y; acc[2] = s.z; acc[3] = s.w;
        } else {
            float2 s = *(const float2*)sp;
            acc[0] = s.x; acc[1] = s.y;
        }
    }

    int e = start;
    for (; e + 4 <= end; e += 4) {
        int u0 = g_csr[e], u1 = g_csr[e + 1], u2 = g_csr[e + 2], u3 = g_csr[e + 3];
        int s0 = u0 & 0x0FFFFFFF, r0 = ((unsigned)u0) >> 28;
        int s1 = u1 & 0x0FFFFFFF, r1 = ((unsigned)u1) >> 28;
        int s2 = u2 & 0x0FFFFFFF, r2 = ((unsigned)u2) >> 28;
        int s3 = u3 & 0x0FFFFFFF, r3 = ((unsigned)u3) >> 28;
        const __half* p0 = g_Ym + (size_t)s0 * PITCH + r0 * OUT + lane * V;
        const __half* p1 = g_Ym + (size_t)s1 * PITCH + r1 * OUT + lane * V;
        const __half* p2 = g_Ym + (size_t)s2 * PITCH + r2 * OUT + lane * V;
        const __half* p3 = g_Ym + (size_t)s3 * PITCH + r3 * OUT + lane * V;
        float i0 = pick4(iv4, r0), i1 = pick4(iv4, r1);
        float i2 = pick4(iv4, r2), i3 = pick4(iv4, r3);
        if constexpr (V == 4) {
            uint2 w0 = *(const uint2*)p0;
            uint2 w1 = *(const uint2*)p1;
            uint2 w2 = *(const uint2*)p2;
            uint2 w3 = *(const uint2*)p3;
            float2 a0 = __half22float2(*(__half2*)&w0.x), a1 = __half22float2(*(__half2*)&w0.y);
            float2 b0 = __half22float2(*(__half2*)&w1.x), b1 = __half22float2(*(__half2*)&w1.y);
            float2 c0 = __half22float2(*(__half2*)&w2.x), c1 = __half22float2(*(__half2*)&w2.y);
            float2 d0 = __half22float2(*(__half2*)&w3.x), d1 = __half22float2(*(__half2*)&w3.y);
            acc[0] += a0.x * i0; acc[1] += a0.y * i0; acc[2] += a1.x * i0; acc[3] += a1.y * i0;
            acc[0] += b0.x * i1; acc[1] += b0.y * i1; acc[2] += b1.x * i1; acc[3] += b1.y * i1;
            acc[0] += c0.x * i2; acc[1] += c0.y * i2; acc[2] += c1.x * i2; acc[3] += c1.y * i2;
            acc[0] += d0.x * i3; acc[1] += d0.y * i3; acc[2] += d1.x * i3; acc[3] += d1.y * i3;
        } else {
            uint32_t w0 = *(const uint32_t*)p0;
            uint32_t w1 = *(const uint32_t*)p1;
            uint32_t w2 = *(const uint32_t*)p2;
            uint32_t w3 = *(const uint32_t*)p3;
            float2 a0 = __half22float2(*(__half2*)&w0);
            float2 b0 = __half22float2(*(__half2*)&w1);
            float2 c0 = __half22float2(*(__half2*)&w2);
            float2 d0 = __half22float2(*(__half2*)&w3);
            acc[0] += a0.x * i0; acc[1] += a0.y * i0;
            acc[0] += b0.x * i1; acc[1] += b0.y * i1;
            acc[0] += c0.x * i2; acc[1] += c0.y * i2;
            acc[0] += d0.x * i3; acc[1] += d0.y * i3;
        }
    }
    for (; e < end; e++) {
        int u0 = g_csr[e];
        int s0 = u0 & 0x0FFFFFFF, r0 = ((unsigned)u0) >> 28;
        const __half* p0 = g_Ym + (size_t)s0 * PITCH + r0 * OUT + lane * V;
        float i0 = pick4(iv4, r0);
        if constexpr (V == 4) {
            uint2 w0 = *(const uint2*)p0;
            float2 a0 = __half22float2(*(__half2*)&w0.x);
            float2 a1 = __half22float2(*(__half2*)&w0.y);
            acc[0] += a0.x * i0; acc[1] += a0.y * i0;
            acc[2] += a1.x * i0; acc[3] += a1.y * i0;
        } else {
            uint32_t w0 = *(const uint32_t*)p0;
            float2 a0 = __half22float2(*(__half2*)&w0);
            acc[0] += a0.x * i0; acc[1] += a0.y * i0;
        }
    }

    if constexpr (MODE == 0) {
        union { __half h[V]; uint2 u2; uint32_t u1; } ph;
#pragma unroll
        for (int j = 0; j < V; j++)
            ph.h[j] = __float2half_rn(fmaxf(acc[j], 0.0f));
        __half* base = g_Asp + (size_t)w * 128 + lane * V;
        if constexpr (V == 4) *(uint2*)base = ph.u2;
        else                  *(uint32_t*)base = ph.u1;
        if constexpr (QF) {
            int b = batch[w];
            __half2 hh;
            hh.x = __float2half_rn(g_q[b * 64 + lane * 2]);
            hh.y = __float2half_rn(g_q[b * 64 + lane * 2 + 1]);
            *(__half2*)(g_Asp + (size_t)w * 128 + 64 + lane * 2) = hh;
        }
    } else {
        float* op = Optr + (size_t)w * OUT + lane * V;
        if constexpr (V == 4) {
            float4 r; r.x = acc[0]; r.y = acc[1]; r.z = acc[2]; r.w = acc[3];
            *(float4*)op = r;
        } else {
            float2 r; r.x = acc[0]; r.y = acc[1];
            *(float2*)op = r;
        }
    }
}

// ---------------- host orchestration ----------------
extern "C" void kernel_launch(void* const* d_in, const int* in_sizes, int n_in,
                              void* d_out, int out_size) {
    const float* x     = (const float*)d_in[0];
    const int*   ei    = (const int*)d_in[1];
    const int*   ea    = (const int*)d_in[2];
    const int*   batch = (const int*)d_in[3];
    const float* qe    = (const float*)d_in[4];
    const float* qnW   = (const float*)d_in[5];
    const float* qnb   = (const float*)d_in[6];
    const float* W0 = (const float*)d_in[7],  *root0 = (const float*)d_in[8],  *b0 = (const float*)d_in[9];
    const float* W1 = (const float*)d_in[10], *root1 = (const float*)d_in[11], *b1 = (const float*)d_in[12];
    const float* W2 = (const float*)d_in[13], *root2 = (const float*)d_in[14], *b2 = (const float*)d_in[15];
    const float* W3 = (const float*)d_in[16], *root3 = (const float*)d_in[17], *b3 = (const float*)d_in[18];
    float* out = (float*)d_out;

    const int* src = ei;
    const int* dst = ei + EE;

    cudaFuncSetAttribute(k_gemm, cudaFuncAttributeMaxDynamicSharedMemorySize, GEMM_SMEM);

    const int MG = 782;                       // ceil(50000/64)
    const int AGG_G = (NN * 32 + 255) / 256;  // 6250

    // k_gemm is launch #4 so ncu -s captures it.
    k_prepA0<<<(NN * 128 + 255) / 256, 256>>>(x);              // 1 (also zeroes g_cnt)
    k_prepB<<<(128 * 320 + 255) / 256, 256>>>(root0, W0, 64);  // 2
    k_q<<<GG, 64>>>(qe, qnW, qnb);                             // 3
    k_gemm<<<MG, 128, GEMM_SMEM>>>(b0, 64, 3);                 // 4 (profiled)
    k_count<<<(EE + 255) / 256, 256>>>(dst, ea);               // 5
    k_scan1<<<196, 256>>>();                                   // 6
    k_scan2<<<1, 256>>>();                                     // 7
    k_scan3<<<196, 256>>>();                                   // 8
    k_fill<<<(EE + 255) / 256, 256>>>(src, dst, ea);           // 9

    // Layer 0 aggregation (+ fused q[batch] fill)
    k_agg<64, 0, 1><<<AGG_G, 256>>>(nullptr, batch);

    // Layer 1: in=128, out=128
    k_prepB<<<(128 * 640 + 255) / 256, 256>>>(root1, W1, 128);
    k_gemm<<<MG, 128, GEMM_SMEM>>>(b1, 128, 5);
    k_agg<128, 0, 0><<<AGG_G, 256>>>(nullptr, nullptr);

    // Layer 2: in=128, out=128
    k_prepB<<<(128 * 640 + 255) / 256, 256>>>(root2, W2, 128);
    k_gemm<<<MG, 128, GEMM_SMEM>>>(b2, 128, 5);
    k_agg<128, 0, 0><<<AGG_G, 256>>>(nullptr, nullptr);

    // Layer 3: in=128, out=64 -> d_out
    k_prepB<<<(128 * 320 + 255) / 256, 256>>>(root3, W3, 64);
    k_gemm<<<MG, 128, GEMM_SMEM>>>(b3, 64, 3);
    k_agg<64, 1, 0><<<AGG_G, 256>>>(out, nullptr);
}